// round 1
// baseline (speedup 1.0000x reference)
#include <cuda_runtime.h>

// Problem dims
#define Bq 16
#define Tq 512
#define Eq 256
#define Aq 8

// Scratch (allocation-free rules: __device__ globals)
__device__ float g_gram[Bq * Tq * Tq];            // masked gram, 16.8 MB
__device__ float g_attn_out[Bq * Aq * Tq * Eq];   // (B,A,T,E) flat, 67 MB
__device__ float g_attn_fb[Bq * Aq * Tq * Tq];    // fallback attn buffer, 134 MB

// GEMM tiling
#define BM 64
#define BN 64
#define BK 16
#define TM 4
#define TN 4
// block = 16x16 = 256 threads

// ---------------------------------------------------------------------------
// Kernel 1: G_b = mask-outer ? (X_b X_b^T)/sqrt(E) : 0
// ---------------------------------------------------------------------------
__global__ void gram_kernel(const float* __restrict__ X, const int* __restrict__ mask) {
    int b = blockIdx.z;
    const float* Xb = X + (size_t)b * Tq * Eq;
    __shared__ float As[BK][BM];
    __shared__ float Bs[BK][BN];
    int tx = threadIdx.x, ty = threadIdx.y;
    int tid = ty * 16 + tx;
    int m0 = blockIdx.y * BM, n0 = blockIdx.x * BN;
    float acc[TM][TN] = {};
    for (int k0 = 0; k0 < Eq; k0 += BK) {
        #pragma unroll
        for (int l = 0; l < 4; ++l) {
            int e = tid * 4 + l;
            int m = e >> 4, k = e & 15;      // 4 consecutive k per thread (coalesced-ish)
            As[k][m] = Xb[(m0 + m) * Eq + k0 + k];
            Bs[k][m] = Xb[(n0 + m) * Eq + k0 + k];
        }
        __syncthreads();
        #pragma unroll
        for (int k = 0; k < BK; ++k) {
            float ra[TM], rb[TN];
            #pragma unroll
            for (int i = 0; i < TM; ++i) ra[i] = As[k][ty * TM + i];
            #pragma unroll
            for (int j = 0; j < TN; ++j) rb[j] = Bs[k][tx * TN + j];
            #pragma unroll
            for (int i = 0; i < TM; ++i)
                #pragma unroll
                for (int j = 0; j < TN; ++j)
                    acc[i][j] += ra[i] * rb[j];
        }
        __syncthreads();
    }
    const int* mb = mask + b * Tq;
    float* G = g_gram + (size_t)b * Tq * Tq;
    #pragma unroll
    for (int i = 0; i < TM; ++i) {
        int m = m0 + ty * TM + i;
        bool mm = (mb[m] != 0);
        #pragma unroll
        for (int j = 0; j < TN; ++j) {
            int n = n0 + tx * TN + j;
            bool mn = (mb[n] != 0);
            G[m * Tq + n] = (mm && mn) ? acc[i][j] * 0.0625f : 0.0f;  // 1/sqrt(256)
        }
    }
}

// ---------------------------------------------------------------------------
// Kernel 2: softmax over rows of s^2 * G for each attribute; one block per (b,t)
// ---------------------------------------------------------------------------
__global__ void softmax_kernel(const float* __restrict__ atr, float* __restrict__ attn) {
    int t = blockIdx.x, b = blockIdx.y;
    int tid = threadIdx.x;  // 256
    __shared__ float red[8];
    const float* g = g_gram + ((size_t)b * Tq + t) * Tq;
    float r0 = g[tid], r1 = g[tid + 256];
    int warp = tid >> 5, lane = tid & 31;

    for (int a = 0; a < Aq; ++a) {
        float s = atr[b * Aq + a];
        float s2 = s * s;
        float v0 = s2 * r0, v1 = s2 * r1;
        // row max
        float m = fmaxf(v0, v1);
        #pragma unroll
        for (int off = 16; off; off >>= 1) m = fmaxf(m, __shfl_xor_sync(0xffffffffu, m, off));
        if (lane == 0) red[warp] = m;
        __syncthreads();
        float mm = red[0];
        #pragma unroll
        for (int w = 1; w < 8; ++w) mm = fmaxf(mm, red[w]);
        __syncthreads();
        // exp + sum
        float e0 = __expf(v0 - mm), e1 = __expf(v1 - mm);
        float ssum = e0 + e1;
        #pragma unroll
        for (int off = 16; off; off >>= 1) ssum += __shfl_xor_sync(0xffffffffu, ssum, off);
        if (lane == 0) red[warp] = ssum;
        __syncthreads();
        float tot = red[0];
        #pragma unroll
        for (int w = 1; w < 8; ++w) tot += red[w];
        float inv = 1.0f / tot;
        float* dst = attn + (((size_t)(b * Aq + a) * Tq) + t) * Tq;
        dst[tid] = e0 * inv;
        dst[tid + 256] = e1 * inv;
        __syncthreads();  // protect red[] before next iteration
    }
}

// ---------------------------------------------------------------------------
// Kernel 3: attn_out[ba] = s_ba * (attn_ba @ X_b)    (512x512 @ 512x256)
// ---------------------------------------------------------------------------
__global__ void av_kernel(const float* __restrict__ X, const float* __restrict__ atr,
                          const float* __restrict__ attn) {
    int ba = blockIdx.z;
    int b = ba >> 3;
    const float* Am = attn + (size_t)ba * Tq * Tq;
    const float* Bm = X + (size_t)b * Tq * Eq;
    __shared__ float As[BK][BM];
    __shared__ float Bs[BK][BN];
    int tx = threadIdx.x, ty = threadIdx.y;
    int tid = ty * 16 + tx;
    int m0 = blockIdx.y * BM, n0 = blockIdx.x * BN;
    float acc[TM][TN] = {};
    for (int k0 = 0; k0 < Tq; k0 += BK) {
        #pragma unroll
        for (int l = 0; l < 4; ++l) {
            int e = tid * 4 + l;
            int m = e >> 4, k = e & 15;
            As[k][m] = Am[(m0 + m) * Tq + k0 + k];
        }
        #pragma unroll
        for (int l = 0; l < 4; ++l) {
            int e = tid * 4 + l;
            int k = e >> 6, n = e & 63;      // 4 consecutive n: coalesced on X
            Bs[k][n] = Bm[(k0 + k) * Eq + n0 + n];
        }
        __syncthreads();
        #pragma unroll
        for (int k = 0; k < BK; ++k) {
            float ra[TM], rb[TN];
            #pragma unroll
            for (int i = 0; i < TM; ++i) ra[i] = As[k][ty * TM + i];
            #pragma unroll
            for (int j = 0; j < TN; ++j) rb[j] = Bs[k][tx * TN + j];
            #pragma unroll
            for (int i = 0; i < TM; ++i)
                #pragma unroll
                for (int j = 0; j < TN; ++j)
                    acc[i][j] += ra[i] * rb[j];
        }
        __syncthreads();
    }
    float s = atr[ba];
    float* Cp = g_attn_out + (size_t)ba * Tq * Eq;
    #pragma unroll
    for (int i = 0; i < TM; ++i) {
        int m = m0 + ty * TM + i;
        #pragma unroll
        for (int j = 0; j < TN; ++j) {
            int n = n0 + tx * TN + j;
            Cp[m * Eq + n] = s * acc[i][j];
        }
    }
}

// ---------------------------------------------------------------------------
// Kernel 4: output = flat_attn_out(8192x2048) @ W^T(2048x256) + bias
// (the reference's reshape(B,T,A*E) is a flat reinterpret of (B,A,T,E))
// ---------------------------------------------------------------------------
__global__ void proj_kernel(const float* __restrict__ W, const float* __restrict__ bias,
                            float* __restrict__ out) {
    const int Kd = Aq * Eq;  // 2048
    __shared__ float As[BK][BM];
    __shared__ float Bs[BK][BN];
    int tx = threadIdx.x, ty = threadIdx.y;
    int tid = ty * 16 + tx;
    int m0 = blockIdx.y * BM, n0 = blockIdx.x * BN;
    float acc[TM][TN] = {};
    for (int k0 = 0; k0 < Kd; k0 += BK) {
        #pragma unroll
        for (int l = 0; l < 4; ++l) {
            int e = tid * 4 + l;
            int m = e >> 4, k = e & 15;
            As[k][m] = g_attn_out[(size_t)(m0 + m) * Kd + k0 + k];
            Bs[k][m] = W[(size_t)(n0 + m) * Kd + k0 + k];  // B[k][n] = W[n*Kd+k]
        }
        __syncthreads();
        #pragma unroll
        for (int k = 0; k < BK; ++k) {
            float ra[TM], rb[TN];
            #pragma unroll
            for (int i = 0; i < TM; ++i) ra[i] = As[k][ty * TM + i];
            #pragma unroll
            for (int j = 0; j < TN; ++j) rb[j] = Bs[k][tx * TN + j];
            #pragma unroll
            for (int i = 0; i < TM; ++i)
                #pragma unroll
                for (int j = 0; j < TN; ++j)
                    acc[i][j] += ra[i] * rb[j];
        }
        __syncthreads();
    }
    #pragma unroll
    for (int i = 0; i < TM; ++i) {
        int m = m0 + ty * TM + i;
        #pragma unroll
        for (int j = 0; j < TN; ++j) {
            int n = n0 + tx * TN + j;
            out[(size_t)m * Eq + n] = acc[i][j] + bias[n];
        }
    }
}

// ---------------------------------------------------------------------------
extern "C" void kernel_launch(void* const* d_in, const int* in_sizes, int n_in,
                              void* d_out, int out_size) {
    const float* sent = (const float*)d_in[0];
    const int*   mask = (const int*)d_in[1];
    const float* atr  = (const float*)d_in[2];
    const float* W    = (const float*)d_in[3];
    const float* bias = (const float*)d_in[4];
    float* out = (float*)d_out;

    const long long OUT_E  = (long long)Bq * Tq * Eq;        // 2,097,152
    const long long ATTN_E = (long long)Bq * Aq * Tq * Tq;   // 33,554,432

    float* attn_ptr;
    if ((long long)out_size >= OUT_E + ATTN_E) {
        attn_ptr = out + OUT_E;                  // tuple (output, attn) flattened
    } else {
        void* p = nullptr;
        cudaGetSymbolAddress(&p, g_attn_fb);     // query only, capture-safe
        attn_ptr = (float*)p;
    }

    dim3 blk(16, 16);
    gram_kernel<<<dim3(Tq / BN, Tq / BM, Bq), blk>>>(sent, mask);
    softmax_kernel<<<dim3(Tq, Bq), 256>>>(atr, attn_ptr);
    av_kernel<<<dim3(Eq / BN, Tq / BM, Bq * Aq), blk>>>(sent, atr, attn_ptr);
    proj_kernel<<<dim3(Eq / BN, (Bq * Tq) / BM, 1), blk>>>(W, bias, out);
}

// round 2
// speedup vs baseline: 1.6077x; 1.6077x over previous
#include <cuda_runtime.h>

// Problem dims
#define Bq 16
#define Tq 512
#define Eq 256
#define Aq 8

// Scratch (allocation-free rules: __device__ globals)
__device__ float g_gram[Bq * Tq * Tq];            // masked gram, 16.8 MB
__device__ float g_attn_out[Bq * Aq * Tq * Eq];   // (B,A,T,E) flat, 67 MB
__device__ float g_attn_fb[Bq * Aq * Tq * Tq];    // fallback attn buffer, 134 MB

// GEMM tiling: 128x128x16, 256 threads, 8x8 per-thread tile
#define BM 128
#define BN 128
#define BK 16

// ---------------------------------------------------------------------------
// Shared GEMM core. A is [m][k] row-major (lda = row stride).
// B_IS_NK=true : B stored [n][k] (row-major over k)  -> needs transpose load
// B_IS_NK=false: B stored [k][n] (row-major over n)  -> direct load
// Accumulates C tile (m0,n0) of size 128x128 into acc[8][8].
// ---------------------------------------------------------------------------
template <bool B_IS_NK>
__device__ __forceinline__ void gemm_core(
    const float* __restrict__ Asrc, int lda,
    const float* __restrict__ Bsrc, int ldb,
    int kBase, int K, int m0, int n0,
    float acc[8][8])
{
    __shared__ float As[BK][BM];
    __shared__ float Bs[BK][BN];
    const int tid = threadIdx.x;           // 0..255
    const int tx = tid & 15;               // n dir
    const int ty = tid >> 4;               // m dir

    // A loader indices: each thread loads 8 floats (2 float4) of one row
    const int a_m  = tid >> 1;             // 0..127
    const int a_kh = (tid & 1) * 8;        // 0 or 8

    // B loader (direct [k][n]) indices
    const int b_k = tid >> 4;              // 0..15
    const int b_n = (tid & 15) * 8;        // 0..120

    for (int k0 = kBase; k0 < kBase + K; k0 += BK) {
        // --- load A tile (transpose to As[k][m]) ---
        {
            const float* p = Asrc + (size_t)(m0 + a_m) * lda + k0 + a_kh;
            float4 v0 = *(const float4*)(p);
            float4 v1 = *(const float4*)(p + 4);
            As[a_kh + 0][a_m] = v0.x; As[a_kh + 1][a_m] = v0.y;
            As[a_kh + 2][a_m] = v0.z; As[a_kh + 3][a_m] = v0.w;
            As[a_kh + 4][a_m] = v1.x; As[a_kh + 5][a_m] = v1.y;
            As[a_kh + 6][a_m] = v1.z; As[a_kh + 7][a_m] = v1.w;
        }
        // --- load B tile ---
        if (B_IS_NK) {
            const float* p = Bsrc + (size_t)(n0 + a_m) * ldb + k0 + a_kh;
            float4 v0 = *(const float4*)(p);
            float4 v1 = *(const float4*)(p + 4);
            Bs[a_kh + 0][a_m] = v0.x; Bs[a_kh + 1][a_m] = v0.y;
            Bs[a_kh + 2][a_m] = v0.z; Bs[a_kh + 3][a_m] = v0.w;
            Bs[a_kh + 4][a_m] = v1.x; Bs[a_kh + 5][a_m] = v1.y;
            Bs[a_kh + 6][a_m] = v1.z; Bs[a_kh + 7][a_m] = v1.w;
        } else {
            const float* p = Bsrc + (size_t)(k0 + b_k) * ldb + n0 + b_n;
            float4 v0 = *(const float4*)(p);
            float4 v1 = *(const float4*)(p + 4);
            *(float4*)&Bs[b_k][b_n]     = v0;
            *(float4*)&Bs[b_k][b_n + 4] = v1;
        }
        __syncthreads();

        #pragma unroll
        for (int k = 0; k < BK; ++k) {
            float4 a0 = *(const float4*)&As[k][ty * 8];
            float4 a1 = *(const float4*)&As[k][ty * 8 + 4];
            float4 b0 = *(const float4*)&Bs[k][tx * 8];
            float4 b1 = *(const float4*)&Bs[k][tx * 8 + 4];
            float ra[8] = {a0.x, a0.y, a0.z, a0.w, a1.x, a1.y, a1.z, a1.w};
            float rb[8] = {b0.x, b0.y, b0.z, b0.w, b1.x, b1.y, b1.z, b1.w};
            #pragma unroll
            for (int i = 0; i < 8; ++i)
                #pragma unroll
                for (int j = 0; j < 8; ++j)
                    acc[i][j] += ra[i] * rb[j];
        }
        __syncthreads();
    }
}

// ---------------------------------------------------------------------------
// Kernel 1: G_b = mask-outer ? (X_b X_b^T)/sqrt(E) : 0     (K=256)
// ---------------------------------------------------------------------------
__global__ __launch_bounds__(256, 2)
void gram_kernel(const float* __restrict__ X, const int* __restrict__ mask) {
    int b = blockIdx.z;
    const float* Xb = X + (size_t)b * Tq * Eq;
    int m0 = blockIdx.y * BM, n0 = blockIdx.x * BN;
    float acc[8][8] = {};
    gemm_core<true>(Xb, Eq, Xb, Eq, 0, Eq, m0, n0, acc);

    const int tx = threadIdx.x & 15, ty = threadIdx.x >> 4;
    const int* mb = mask + b * Tq;
    float* G = g_gram + (size_t)b * Tq * Tq;
    #pragma unroll
    for (int i = 0; i < 8; ++i) {
        int m = m0 + ty * 8 + i;
        float sm = (mb[m] != 0) ? 0.0625f : 0.0f;   // 1/sqrt(256), fold mask
        float o[8];
        #pragma unroll
        for (int j = 0; j < 8; ++j) {
            int n = n0 + tx * 8 + j;
            o[j] = (mb[n] != 0) ? acc[i][j] * sm : 0.0f;
        }
        *(float4*)&G[(size_t)m * Tq + n0 + tx * 8]     = make_float4(o[0], o[1], o[2], o[3]);
        *(float4*)&G[(size_t)m * Tq + n0 + tx * 8 + 4] = make_float4(o[4], o[5], o[6], o[7]);
    }
}

// ---------------------------------------------------------------------------
// Kernel 2: softmax over rows of s^2 * G for each attribute; one block per (b,t)
// ---------------------------------------------------------------------------
__global__ void softmax_kernel(const float* __restrict__ atr, float* __restrict__ attn) {
    int t = blockIdx.x, b = blockIdx.y;
    int tid = threadIdx.x;  // 256
    __shared__ float red[8];
    const float* g = g_gram + ((size_t)b * Tq + t) * Tq;
    float r0 = g[tid], r1 = g[tid + 256];
    int warp = tid >> 5, lane = tid & 31;

    for (int a = 0; a < Aq; ++a) {
        float s = atr[b * Aq + a];
        float s2 = s * s;
        float v0 = s2 * r0, v1 = s2 * r1;
        float m = fmaxf(v0, v1);
        #pragma unroll
        for (int off = 16; off; off >>= 1) m = fmaxf(m, __shfl_xor_sync(0xffffffffu, m, off));
        if (lane == 0) red[warp] = m;
        __syncthreads();
        float mm = red[0];
        #pragma unroll
        for (int w = 1; w < 8; ++w) mm = fmaxf(mm, red[w]);
        __syncthreads();
        float e0 = __expf(v0 - mm), e1 = __expf(v1 - mm);
        float ssum = e0 + e1;
        #pragma unroll
        for (int off = 16; off; off >>= 1) ssum += __shfl_xor_sync(0xffffffffu, ssum, off);
        if (lane == 0) red[warp] = ssum;
        __syncthreads();
        float tot = red[0];
        #pragma unroll
        for (int w = 1; w < 8; ++w) tot += red[w];
        float inv = 1.0f / tot;
        float* dst = attn + (((size_t)(b * Aq + a) * Tq) + t) * Tq;
        dst[tid] = e0 * inv;
        dst[tid + 256] = e1 * inv;
        __syncthreads();
    }
}

// ---------------------------------------------------------------------------
// Kernel 3: attn_out[ba] = s_ba * (attn_ba @ X_b)    (512x256, K=512)
// ---------------------------------------------------------------------------
__global__ __launch_bounds__(256, 2)
void av_kernel(const float* __restrict__ X, const float* __restrict__ atr,
               const float* __restrict__ attn) {
    int ba = blockIdx.z;
    int b = ba >> 3;
    const float* Am = attn + (size_t)ba * Tq * Tq;
    const float* Bm = X + (size_t)b * Tq * Eq;
    int m0 = blockIdx.y * BM, n0 = blockIdx.x * BN;
    float acc[8][8] = {};
    gemm_core<false>(Am, Tq, Bm, Eq, 0, Tq, m0, n0, acc);

    const int tx = threadIdx.x & 15, ty = threadIdx.x >> 4;
    float s = atr[ba];
    float* Cp = g_attn_out + (size_t)ba * Tq * Eq;
    #pragma unroll
    for (int i = 0; i < 8; ++i) {
        int m = m0 + ty * 8 + i;
        float o[8];
        #pragma unroll
        for (int j = 0; j < 8; ++j) o[j] = s * acc[i][j];
        *(float4*)&Cp[(size_t)m * Eq + n0 + tx * 8]     = make_float4(o[0], o[1], o[2], o[3]);
        *(float4*)&Cp[(size_t)m * Eq + n0 + tx * 8 + 4] = make_float4(o[4], o[5], o[6], o[7]);
    }
}

// ---------------------------------------------------------------------------
// Kernel 4a: out = bias (init)
// ---------------------------------------------------------------------------
__global__ void bias_init_kernel(const float* __restrict__ bias, float* __restrict__ out) {
    int idx = blockIdx.x * 256 + threadIdx.x;              // over B*T*E/4
    float4 bv = *(const float4*)&bias[(idx & 63) * 4];     // Eq/4=64 float4 per row
    ((float4*)out)[idx] = bv;
}

// ---------------------------------------------------------------------------
// Kernel 4b: out += flat_attn_out(8192x2048) @ W^T(2048x256), split-K=2
// ---------------------------------------------------------------------------
__global__ __launch_bounds__(256, 2)
void proj_kernel(const float* __restrict__ W, float* __restrict__ out) {
    const int Kd = Aq * Eq;  // 2048
    const int KS = Kd / 2;   // split-K half
    int m0 = blockIdx.y * BM, n0 = blockIdx.x * BN;
    int kBase = blockIdx.z * KS;
    float acc[8][8] = {};
    gemm_core<true>(g_attn_out, Kd, W, Kd, kBase, KS, m0, n0, acc);

    const int tx = threadIdx.x & 15, ty = threadIdx.x >> 4;
    #pragma unroll
    for (int i = 0; i < 8; ++i) {
        int m = m0 + ty * 8 + i;
        #pragma unroll
        for (int j = 0; j < 8; ++j) {
            int n = n0 + tx * 8 + j;
            atomicAdd(&out[(size_t)m * Eq + n], acc[i][j]);
        }
    }
}

// ---------------------------------------------------------------------------
extern "C" void kernel_launch(void* const* d_in, const int* in_sizes, int n_in,
                              void* d_out, int out_size) {
    const float* sent = (const float*)d_in[0];
    const int*   mask = (const int*)d_in[1];
    const float* atr  = (const float*)d_in[2];
    const float* W    = (const float*)d_in[3];
    const float* bias = (const float*)d_in[4];
    float* out = (float*)d_out;

    const long long OUT_E  = (long long)Bq * Tq * Eq;        // 2,097,152
    const long long ATTN_E = (long long)Bq * Aq * Tq * Tq;   // 33,554,432

    float* attn_ptr;
    if ((long long)out_size >= OUT_E + ATTN_E) {
        attn_ptr = out + OUT_E;                  // tuple (output, attn) flattened
    } else {
        void* p = nullptr;
        cudaGetSymbolAddress(&p, g_attn_fb);     // query only, capture-safe
        attn_ptr = (float*)p;
    }

    gram_kernel<<<dim3(Tq / BN, Tq / BM, Bq), 256>>>(sent, mask);
    softmax_kernel<<<dim3(Tq, Bq), 256>>>(atr, attn_ptr);
    av_kernel<<<dim3(Eq / BN, Tq / BM, Bq * Aq), 256>>>(sent, atr, attn_ptr);
    bias_init_kernel<<<(Bq * Tq * Eq / 4) / 256, 256>>>(bias, out);
    proj_kernel<<<dim3(Eq / BN, (Bq * Tq) / BM, 2), 256>>>(W, out);
}

// round 3
// speedup vs baseline: 2.6301x; 1.6360x over previous
#include <cuda_runtime.h>
#include <cuda_bf16.h>

// Problem dims
#define Bq 16
#define Tq 512
#define Eq 256
#define Aq 8

// Scratch (allocation-free rules: __device__ globals)
__device__ float g_gram[Bq * Tq * Tq];            // masked gram, 16.8 MB
__device__ float g_xt[Bq * Eq * Tq];              // X transposed (B,E,T), 8 MB
__device__ float g_attn_out[Bq * Aq * Tq * Eq];   // (B,A,T,E) flat, 67 MB
__device__ float g_attn_fb[Bq * Aq * Tq * Tq];    // fallback attn buffer, 134 MB

// MMA GEMM tiling: 128x128 CTA tile, BK=32 (fp32 k elems per stage), 256 threads
#define BMm 128
#define BNm 128
#define BKm 32
// smem rows hold 16 bf16 pairs (32 elems) + 1 pad pair -> 34 ushorts = 68B stride
struct Smem {
    ushort Ah[128][34];
    ushort Al[128][34];
    ushort Bh[128][34];
    ushort Bl[128][34];
};

// ---------------------------------------------------------------------------
// mma.sync m16n8k16 bf16 (row.col), fp32 accumulate
// ---------------------------------------------------------------------------
__device__ __forceinline__ void mma16816(float* c, const unsigned* a, const unsigned* b) {
    asm volatile(
        "mma.sync.aligned.m16n8k16.row.col.f32.bf16.bf16.f32 "
        "{%0,%1,%2,%3}, {%4,%5,%6,%7}, {%8,%9}, {%0,%1,%2,%3};"
        : "+f"(c[0]), "+f"(c[1]), "+f"(c[2]), "+f"(c[3])
        : "r"(a[0]), "r"(a[1]), "r"(a[2]), "r"(a[3]), "r"(b[0]), "r"(b[1]));
}

// Global load: one 128x32 fp32 tile each for A and B (both row-major over k)
__device__ __forceinline__ void gload(
    const float* __restrict__ A, int lda, int m0,
    const float* __restrict__ B, int ldb, int n0,
    int k0, int r, int kh, float4* ra, float4* rb)
{
    const float* pa = A + (size_t)(m0 + r) * lda + k0 + kh;
    const float* pb = B + (size_t)(n0 + r) * ldb + k0 + kh;
    #pragma unroll
    for (int q = 0; q < 4; ++q) {
        ra[q] = *(const float4*)(pa + 4 * q);
        rb[q] = *(const float4*)(pb + 4 * q);
    }
}

// Split fp32 -> (hi, lo) bf16 pairs and store to smem
__device__ __forceinline__ void sts_split(
    ushort (*Sh)[34], ushort (*Sl)[34], int r, int pi0, const float4* v4)
{
    #pragma unroll
    for (int q = 0; q < 4; ++q) {
        float4 v = v4[q];
        __nv_bfloat162 h0 = __float22bfloat162_rn(make_float2(v.x, v.y));
        __nv_bfloat162 h1 = __float22bfloat162_rn(make_float2(v.z, v.w));
        __nv_bfloat162 l0 = __float22bfloat162_rn(
            make_float2(v.x - __low2float(h0), v.y - __high2float(h0)));
        __nv_bfloat162 l1 = __float22bfloat162_rn(
            make_float2(v.z - __low2float(h1), v.w - __high2float(h1)));
        int p = pi0 + 2 * q;
        *(unsigned*)&Sh[r][2 * p]     = *(unsigned*)&h0;
        *(unsigned*)&Sh[r][2 * p + 2] = *(unsigned*)&h1;
        *(unsigned*)&Sl[r][2 * p]     = *(unsigned*)&l0;
        *(unsigned*)&Sl[r][2 * p + 2] = *(unsigned*)&l1;
    }
}

// ---------------------------------------------------------------------------
// Core: acc[2][8][4] += A(128xK) * B^T where B rows are n over k.
// Both A and B must be row-major over k. 3-pass split-bf16 (~fp32 accuracy).
// ---------------------------------------------------------------------------
__device__ __forceinline__ void gemm_bf16x3(
    const float* __restrict__ A, int lda, int m0,
    const float* __restrict__ B, int ldb, int n0,
    int kBase, int kIters, float acc[2][8][4], Smem& s)
{
    const int t = threadIdx.x;
    const int r  = t >> 1;
    const int kh = (t & 1) * 16;
    const int lane = t & 31, wid = t >> 5;
    const int gid = lane >> 2, tig = lane & 3;
    const int mw = (wid >> 1) * 32, nw = (wid & 1) * 64;

    float4 ra[4], rb[4];
    gload(A, lda, m0, B, ldb, n0, kBase, r, kh, ra, rb);

    for (int it = 0; it < kIters; ++it) {
        sts_split(s.Ah, s.Al, r, kh >> 1, ra);
        sts_split(s.Bh, s.Bl, r, kh >> 1, rb);
        __syncthreads();
        if (it + 1 < kIters)  // prefetch next tiles; LDG overlaps MMA below
            gload(A, lda, m0, B, ldb, n0, kBase + (it + 1) * BKm, r, kh, ra, rb);

        #pragma unroll
        for (int ks = 0; ks < 2; ++ks) {
            const int kp = ks * 8;  // pair offset within stage
            unsigned ah[2][4], al[2][4];
            #pragma unroll
            for (int mt = 0; mt < 2; ++mt) {
                int r0 = mw + mt * 16 + gid;
                ah[mt][0] = *(unsigned*)&s.Ah[r0][2 * (kp + tig)];
                ah[mt][1] = *(unsigned*)&s.Ah[r0 + 8][2 * (kp + tig)];
                ah[mt][2] = *(unsigned*)&s.Ah[r0][2 * (kp + tig + 4)];
                ah[mt][3] = *(unsigned*)&s.Ah[r0 + 8][2 * (kp + tig + 4)];
                al[mt][0] = *(unsigned*)&s.Al[r0][2 * (kp + tig)];
                al[mt][1] = *(unsigned*)&s.Al[r0 + 8][2 * (kp + tig)];
                al[mt][2] = *(unsigned*)&s.Al[r0][2 * (kp + tig + 4)];
                al[mt][3] = *(unsigned*)&s.Al[r0 + 8][2 * (kp + tig + 4)];
            }
            #pragma unroll
            for (int nt = 0; nt < 8; ++nt) {
                int rn = nw + nt * 8 + gid;
                unsigned bh[2], bl[2];
                bh[0] = *(unsigned*)&s.Bh[rn][2 * (kp + tig)];
                bh[1] = *(unsigned*)&s.Bh[rn][2 * (kp + tig + 4)];
                bl[0] = *(unsigned*)&s.Bl[rn][2 * (kp + tig)];
                bl[1] = *(unsigned*)&s.Bl[rn][2 * (kp + tig + 4)];
                #pragma unroll
                for (int mt = 0; mt < 2; ++mt) {
                    mma16816(acc[mt][nt], ah[mt], bh);
                    mma16816(acc[mt][nt], ah[mt], bl);
                    mma16816(acc[mt][nt], al[mt], bh);
                }
            }
        }
        __syncthreads();
    }
}

// ---------------------------------------------------------------------------
// Kernel 0: transpose X (B,T,E) -> Xt (B,E,T)
// ---------------------------------------------------------------------------
__global__ void transpose_kernel(const float* __restrict__ X) {
    __shared__ float tile[32][33];
    int b = blockIdx.z;
    int e0 = blockIdx.x * 32, t0 = blockIdx.y * 32;
    const float* Xb = X + (size_t)b * Tq * Eq;
    float* Xtb = g_xt + (size_t)b * Eq * Tq;
    int tx = threadIdx.x, ty = threadIdx.y;  // 32x8
    #pragma unroll
    for (int i = 0; i < 32; i += 8)
        tile[ty + i][tx] = Xb[(size_t)(t0 + ty + i) * Eq + e0 + tx];
    __syncthreads();
    #pragma unroll
    for (int i = 0; i < 32; i += 8)
        Xtb[(size_t)(e0 + ty + i) * Tq + t0 + tx] = tile[tx][ty + i];
}

// ---------------------------------------------------------------------------
// Kernel 1: G_b = mask-outer ? (X_b X_b^T)/sqrt(E) : 0     (K=256)
// ---------------------------------------------------------------------------
__global__ __launch_bounds__(256, 1)
void gram_kernel(const float* __restrict__ X, const int* __restrict__ mask) {
    __shared__ Smem s;
    int b = blockIdx.z;
    const float* Xb = X + (size_t)b * Tq * Eq;
    int m0 = blockIdx.y * BMm, n0 = blockIdx.x * BNm;
    float acc[2][8][4] = {};
    gemm_bf16x3(Xb, Eq, m0, Xb, Eq, n0, 0, Eq / BKm, acc, s);

    const int lane = threadIdx.x & 31, wid = threadIdx.x >> 5;
    const int gid = lane >> 2, tig = lane & 3;
    const int mw = (wid >> 1) * 32, nw = (wid & 1) * 64;
    const int* mb = mask + b * Tq;
    float* G = g_gram + (size_t)b * Tq * Tq;
    #pragma unroll
    for (int mt = 0; mt < 2; ++mt) {
        int mr0 = m0 + mw + mt * 16 + gid;
        int mr1 = mr0 + 8;
        float s0 = (mb[mr0] != 0) ? 0.0625f : 0.0f;
        float s1 = (mb[mr1] != 0) ? 0.0625f : 0.0f;
        #pragma unroll
        for (int nt = 0; nt < 8; ++nt) {
            int col = n0 + nw + nt * 8 + 2 * tig;
            float c0 = (mb[col] != 0) ? 1.0f : 0.0f;
            float c1 = (mb[col + 1] != 0) ? 1.0f : 0.0f;
            float2 v0 = make_float2(acc[mt][nt][0] * s0 * c0, acc[mt][nt][1] * s0 * c1);
            float2 v1 = make_float2(acc[mt][nt][2] * s1 * c0, acc[mt][nt][3] * s1 * c1);
            *(float2*)&G[(size_t)mr0 * Tq + col] = v0;
            *(float2*)&G[(size_t)mr1 * Tq + col] = v1;
        }
    }
}

// ---------------------------------------------------------------------------
// Kernel 2: softmax over rows of s^2 * G; one block per (b,t)
// ---------------------------------------------------------------------------
__global__ void softmax_kernel(const float* __restrict__ atr, float* __restrict__ attn) {
    int t = blockIdx.x, b = blockIdx.y;
    int tid = threadIdx.x;  // 256
    __shared__ float red[8];
    const float* g = g_gram + ((size_t)b * Tq + t) * Tq;
    float r0 = g[tid], r1 = g[tid + 256];
    int warp = tid >> 5, lane = tid & 31;

    for (int a = 0; a < Aq; ++a) {
        float s = atr[b * Aq + a];
        float s2 = s * s;
        float v0 = s2 * r0, v1 = s2 * r1;
        float m = fmaxf(v0, v1);
        #pragma unroll
        for (int off = 16; off; off >>= 1) m = fmaxf(m, __shfl_xor_sync(0xffffffffu, m, off));
        if (lane == 0) red[warp] = m;
        __syncthreads();
        float mm = red[0];
        #pragma unroll
        for (int w = 1; w < 8; ++w) mm = fmaxf(mm, red[w]);
        __syncthreads();
        float e0 = __expf(v0 - mm), e1 = __expf(v1 - mm);
        float ssum = e0 + e1;
        #pragma unroll
        for (int off = 16; off; off >>= 1) ssum += __shfl_xor_sync(0xffffffffu, ssum, off);
        if (lane == 0) red[warp] = ssum;
        __syncthreads();
        float tot = red[0];
        #pragma unroll
        for (int w = 1; w < 8; ++w) tot += red[w];
        float inv = 1.0f / tot;
        float* dst = attn + (((size_t)(b * Aq + a) * Tq) + t) * Tq;
        dst[tid] = e0 * inv;
        dst[tid + 256] = e1 * inv;
        __syncthreads();
    }
}

// ---------------------------------------------------------------------------
// Kernel 3: attn_out[ba] = s_ba * (attn_ba @ X_b)   A=attn (m=t,k=s), B=Xt (n=e,k=s)
// ---------------------------------------------------------------------------
__global__ __launch_bounds__(256, 1)
void av_kernel(const float* __restrict__ atr, const float* __restrict__ attn) {
    __shared__ Smem s;
    int ba = blockIdx.z;
    int b = ba >> 3;
    const float* Am = attn + (size_t)ba * Tq * Tq;
    const float* Bm = g_xt + (size_t)b * Eq * Tq;
    int m0 = blockIdx.y * BMm, n0 = blockIdx.x * BNm;
    float acc[2][8][4] = {};
    gemm_bf16x3(Am, Tq, m0, Bm, Tq, n0, 0, Tq / BKm, acc, s);

    const int lane = threadIdx.x & 31, wid = threadIdx.x >> 5;
    const int gid = lane >> 2, tig = lane & 3;
    const int mw = (wid >> 1) * 32, nw = (wid & 1) * 64;
    float sc = atr[ba];
    float* Cp = g_attn_out + (size_t)ba * Tq * Eq;
    #pragma unroll
    for (int mt = 0; mt < 2; ++mt) {
        int mr0 = m0 + mw + mt * 16 + gid;
        int mr1 = mr0 + 8;
        #pragma unroll
        for (int nt = 0; nt < 8; ++nt) {
            int col = n0 + nw + nt * 8 + 2 * tig;
            float2 v0 = make_float2(sc * acc[mt][nt][0], sc * acc[mt][nt][1]);
            float2 v1 = make_float2(sc * acc[mt][nt][2], sc * acc[mt][nt][3]);
            *(float2*)&Cp[(size_t)mr0 * Eq + col] = v0;
            *(float2*)&Cp[(size_t)mr1 * Eq + col] = v1;
        }
    }
}

// ---------------------------------------------------------------------------
// Kernel 4a: out = bias (init)
// ---------------------------------------------------------------------------
__global__ void bias_init_kernel(const float* __restrict__ bias, float* __restrict__ out) {
    int idx = blockIdx.x * 256 + threadIdx.x;
    float4 bv = *(const float4*)&bias[(idx & 63) * 4];
    ((float4*)out)[idx] = bv;
}

// ---------------------------------------------------------------------------
// Kernel 4b: out += flat_attn_out(8192x2048) @ W^T(2048x256), split-K=2
// ---------------------------------------------------------------------------
__global__ __launch_bounds__(256, 1)
void proj_kernel(const float* __restrict__ W, float* __restrict__ out) {
    __shared__ Smem s;
    const int Kd = Aq * Eq;   // 2048
    const int KS = Kd / 2;    // 1024 per split
    int m0 = blockIdx.y * BMm, n0 = blockIdx.x * BNm;
    int kBase = blockIdx.z * KS;
    float acc[2][8][4] = {};
    gemm_bf16x3(g_attn_out, Kd, m0, W, Kd, n0, kBase, KS / BKm, acc, s);

    const int lane = threadIdx.x & 31, wid = threadIdx.x >> 5;
    const int gid = lane >> 2, tig = lane & 3;
    const int mw = (wid >> 1) * 32, nw = (wid & 1) * 64;
    #pragma unroll
    for (int mt = 0; mt < 2; ++mt) {
        int mr0 = m0 + mw + mt * 16 + gid;
        int mr1 = mr0 + 8;
        #pragma unroll
        for (int nt = 0; nt < 8; ++nt) {
            int col = n0 + nw + nt * 8 + 2 * tig;
            atomicAdd(&out[(size_t)mr0 * Eq + col],     acc[mt][nt][0]);
            atomicAdd(&out[(size_t)mr0 * Eq + col + 1], acc[mt][nt][1]);
            atomicAdd(&out[(size_t)mr1 * Eq + col],     acc[mt][nt][2]);
            atomicAdd(&out[(size_t)mr1 * Eq + col + 1], acc[mt][nt][3]);
        }
    }
}

// ---------------------------------------------------------------------------
extern "C" void kernel_launch(void* const* d_in, const int* in_sizes, int n_in,
                              void* d_out, int out_size) {
    const float* sent = (const float*)d_in[0];
    const int*   mask = (const int*)d_in[1];
    const float* atr  = (const float*)d_in[2];
    const float* W    = (const float*)d_in[3];
    const float* bias = (const float*)d_in[4];
    float* out = (float*)d_out;

    const long long OUT_E  = (long long)Bq * Tq * Eq;        // 2,097,152
    const long long ATTN_E = (long long)Bq * Aq * Tq * Tq;   // 33,554,432

    float* attn_ptr;
    if ((long long)out_size >= OUT_E + ATTN_E) {
        attn_ptr = out + OUT_E;                  // tuple (output, attn) flattened
    } else {
        void* p = nullptr;
        cudaGetSymbolAddress(&p, g_attn_fb);     // query only, capture-safe
        attn_ptr = (float*)p;
    }

    transpose_kernel<<<dim3(Eq / 32, Tq / 32, Bq), dim3(32, 8)>>>(sent);
    gram_kernel<<<dim3(Tq / BNm, Tq / BMm, Bq), 256>>>(sent, mask);
    softmax_kernel<<<dim3(Tq, Bq), 256>>>(atr, attn_ptr);
    av_kernel<<<dim3(Eq / BNm, Tq / BMm, Bq * Aq), 256>>>(atr, attn_ptr);
    bias_init_kernel<<<(Bq * Tq * Eq / 4) / 256, 256>>>(bias, out);
    proj_kernel<<<dim3(Eq / BNm, (Bq * Tq) / BMm, 2), 256>>>(W, out);
}

// round 4
// speedup vs baseline: 3.4288x; 1.3037x over previous
#include <cuda_runtime.h>
#include <cuda_bf16.h>

// Problem dims
#define Bq 16
#define Tq 512
#define Eq 256
#define Aq 8

// Scratch (allocation-free rules: __device__ globals)
__device__ float g_gram[Bq * Tq * Tq];            // masked gram, 16.8 MB
__device__ float g_xt[Bq * Eq * Tq];              // X transposed (B,E,T), 8 MB
__device__ float g_attn_out[Bq * Aq * Tq * Eq];   // (B,A,T,E) flat, 67 MB
__device__ float g_attn_fb[Bq * Aq * Tq * Tq];    // fallback attn buffer, 134 MB

// MMA GEMM tiling: 128x128 CTA tile, BK=32 fp32 elems per stage, 256 threads
#define BMm 128
#define BNm 128
#define BKm 32
// smem rows: 32 bf16 (64B) + 8 pad -> 40 ushorts = 80B stride.
// 80B = 20-bank step: 8 consecutive rows hit disjoint 4-bank groups -> LDSM conflict-free.
struct alignas(16) Smem {
    ushort Ah[128][40];
    ushort Al[128][40];
    ushort Bh[128][40];
    ushort Bl[128][40];
};

// ---------------------------------------------------------------------------
__device__ __forceinline__ void mma16816(float* c, const unsigned* a, const unsigned* b) {
    asm volatile(
        "mma.sync.aligned.m16n8k16.row.col.f32.bf16.bf16.f32 "
        "{%0,%1,%2,%3}, {%4,%5,%6,%7}, {%8,%9}, {%0,%1,%2,%3};"
        : "+f"(c[0]), "+f"(c[1]), "+f"(c[2]), "+f"(c[3])
        : "r"(a[0]), "r"(a[1]), "r"(a[2]), "r"(a[3]), "r"(b[0]), "r"(b[1]));
}

__device__ __forceinline__ void ldsm_x4(unsigned& r0, unsigned& r1, unsigned& r2,
                                        unsigned& r3, unsigned addr) {
    asm volatile("ldmatrix.sync.aligned.m8n8.x4.shared.b16 {%0,%1,%2,%3}, [%4];"
                 : "=r"(r0), "=r"(r1), "=r"(r2), "=r"(r3) : "r"(addr));
}

// Global load: one 128x32 fp32 tile each for A and B (both row-major over k)
__device__ __forceinline__ void gload(
    const float* __restrict__ A, int lda, int m0,
    const float* __restrict__ B, int ldb, int n0,
    int k0, int r, int kh, float4* ra, float4* rb)
{
    const float* pa = A + (size_t)(m0 + r) * lda + k0 + kh;
    const float* pb = B + (size_t)(n0 + r) * ldb + k0 + kh;
    #pragma unroll
    for (int q = 0; q < 4; ++q) {
        ra[q] = *(const float4*)(pa + 4 * q);
        rb[q] = *(const float4*)(pb + 4 * q);
    }
}

// Split fp32 -> (hi, lo) bf16 and store to smem (uint2 stores)
__device__ __forceinline__ void sts_split(
    ushort (*Sh)[40], ushort (*Sl)[40], int r, int c0, const float4* v4)
{
    #pragma unroll
    for (int q = 0; q < 4; ++q) {
        float4 v = v4[q];
        __nv_bfloat162 h0 = __float22bfloat162_rn(make_float2(v.x, v.y));
        __nv_bfloat162 h1 = __float22bfloat162_rn(make_float2(v.z, v.w));
        __nv_bfloat162 l0 = __float22bfloat162_rn(
            make_float2(v.x - __low2float(h0), v.y - __high2float(h0)));
        __nv_bfloat162 l1 = __float22bfloat162_rn(
            make_float2(v.z - __low2float(h1), v.w - __high2float(h1)));
        uint2 hv = make_uint2(*(unsigned*)&h0, *(unsigned*)&h1);
        uint2 lv = make_uint2(*(unsigned*)&l0, *(unsigned*)&l1);
        *(uint2*)&Sh[r][c0 + 4 * q] = hv;
        *(uint2*)&Sl[r][c0 + 4 * q] = lv;
    }
}

// ---------------------------------------------------------------------------
// Core: acc[2][8][4] += A(128xK) * B^T ; both operands row-major over k.
// 3-pass split-bf16 (~fp32 accuracy), ldmatrix fragment fetch.
// ---------------------------------------------------------------------------
__device__ __forceinline__ void gemm_bf16x3(
    const float* __restrict__ A, int lda, int m0,
    const float* __restrict__ B, int ldb, int n0,
    int kBase, int kIters, float acc[2][8][4], Smem& s)
{
    const int t = threadIdx.x;
    const int r  = t >> 1;
    const int kh = (t & 1) * 16;
    const int lane = t & 31, wid = t >> 5;
    const int mw = (wid >> 1) * 32, nw = (wid & 1) * 64;

    // ldmatrix lane geometry
    const int lr = lane & 7, q = lane >> 3;
    // A blocks: q0:(m,k) q1:(m+8,k) q2:(m,k+8) q3:(m+8,k+8)
    const int a_row_off = lr + (q & 1) * 8;
    const int a_col_off = (q >> 1) * 8;
    // B blocks: q0:(n,k) q1:(n,k+8) q2:(n+8,k) q3:(n+8,k+8)
    const int b_row_off = lr + (q >> 1) * 8;
    const int b_col_off = (q & 1) * 8;

    float4 ra[4], rb[4];
    gload(A, lda, m0, B, ldb, n0, kBase, r, kh, ra, rb);

    for (int it = 0; it < kIters; ++it) {
        sts_split(s.Ah, s.Al, r, kh, ra);
        sts_split(s.Bh, s.Bl, r, kh, rb);
        __syncthreads();
        if (it + 1 < kIters)  // register prefetch; LDG overlaps MMA below
            gload(A, lda, m0, B, ldb, n0, kBase + (it + 1) * BKm, r, kh, ra, rb);

        #pragma unroll
        for (int ks = 0; ks < 2; ++ks) {
            const int k0 = ks * 16;
            unsigned ah[2][4], al[2][4];
            #pragma unroll
            for (int mt = 0; mt < 2; ++mt) {
                int rowa = mw + mt * 16 + a_row_off;
                unsigned addr_h = (unsigned)__cvta_generic_to_shared(&s.Ah[rowa][k0 + a_col_off]);
                unsigned addr_l = (unsigned)__cvta_generic_to_shared(&s.Al[rowa][k0 + a_col_off]);
                ldsm_x4(ah[mt][0], ah[mt][1], ah[mt][2], ah[mt][3], addr_h);
                ldsm_x4(al[mt][0], al[mt][1], al[mt][2], al[mt][3], addr_l);
            }
            unsigned bh[8][2], bl[8][2];
            #pragma unroll
            for (int np = 0; np < 4; ++np) {
                int rowb = nw + np * 16 + b_row_off;
                unsigned addr_h = (unsigned)__cvta_generic_to_shared(&s.Bh[rowb][k0 + b_col_off]);
                unsigned addr_l = (unsigned)__cvta_generic_to_shared(&s.Bl[rowb][k0 + b_col_off]);
                ldsm_x4(bh[2*np][0], bh[2*np][1], bh[2*np+1][0], bh[2*np+1][1], addr_h);
                ldsm_x4(bl[2*np][0], bl[2*np][1], bl[2*np+1][0], bl[2*np+1][1], addr_l);
            }
            #pragma unroll
            for (int nt = 0; nt < 8; ++nt)
                #pragma unroll
                for (int mt = 0; mt < 2; ++mt) {
                    mma16816(acc[mt][nt], ah[mt], bh[nt]);
                    mma16816(acc[mt][nt], ah[mt], bl[nt]);
                    mma16816(acc[mt][nt], al[mt], bh[nt]);
                }
        }
        __syncthreads();
    }
}

// ---------------------------------------------------------------------------
// Kernel 0: transpose X (B,T,E) -> Xt (B,E,T)
// ---------------------------------------------------------------------------
__global__ void transpose_kernel(const float* __restrict__ X) {
    __shared__ float tile[32][33];
    int b = blockIdx.z;
    int e0 = blockIdx.x * 32, t0 = blockIdx.y * 32;
    const float* Xb = X + (size_t)b * Tq * Eq;
    float* Xtb = g_xt + (size_t)b * Eq * Tq;
    int tx = threadIdx.x, ty = threadIdx.y;  // 32x8
    #pragma unroll
    for (int i = 0; i < 32; i += 8)
        tile[ty + i][tx] = Xb[(size_t)(t0 + ty + i) * Eq + e0 + tx];
    __syncthreads();
    #pragma unroll
    for (int i = 0; i < 32; i += 8)
        Xtb[(size_t)(e0 + ty + i) * Tq + t0 + tx] = tile[tx][ty + i];
}

// ---------------------------------------------------------------------------
// Kernel 1: G_b = mask-outer ? (X_b X_b^T)/sqrt(E) : 0     (K=256)
// ---------------------------------------------------------------------------
__global__ __launch_bounds__(256, 1)
void gram_kernel(const float* __restrict__ X, const int* __restrict__ mask) {
    __shared__ Smem s;
    int b = blockIdx.z;
    const float* Xb = X + (size_t)b * Tq * Eq;
    int m0 = blockIdx.y * BMm, n0 = blockIdx.x * BNm;
    float acc[2][8][4] = {};
    gemm_bf16x3(Xb, Eq, m0, Xb, Eq, n0, 0, Eq / BKm, acc, s);

    const int lane = threadIdx.x & 31, wid = threadIdx.x >> 5;
    const int gid = lane >> 2, tig = lane & 3;
    const int mw = (wid >> 1) * 32, nw = (wid & 1) * 64;
    const int* mb = mask + b * Tq;
    float* G = g_gram + (size_t)b * Tq * Tq;
    #pragma unroll
    for (int mt = 0; mt < 2; ++mt) {
        int mr0 = m0 + mw + mt * 16 + gid;
        int mr1 = mr0 + 8;
        float s0 = (mb[mr0] != 0) ? 0.0625f : 0.0f;
        float s1 = (mb[mr1] != 0) ? 0.0625f : 0.0f;
        #pragma unroll
        for (int nt = 0; nt < 8; ++nt) {
            int col = n0 + nw + nt * 8 + 2 * tig;
            float c0 = (mb[col] != 0) ? 1.0f : 0.0f;
            float c1 = (mb[col + 1] != 0) ? 1.0f : 0.0f;
            float2 v0 = make_float2(acc[mt][nt][0] * s0 * c0, acc[mt][nt][1] * s0 * c1);
            float2 v1 = make_float2(acc[mt][nt][2] * s1 * c0, acc[mt][nt][3] * s1 * c1);
            *(float2*)&G[(size_t)mr0 * Tq + col] = v0;
            *(float2*)&G[(size_t)mr1 * Tq + col] = v1;
        }
    }
}

// ---------------------------------------------------------------------------
// Kernel 2: softmax over rows of s^2 * G; one block per (b,t)
// ---------------------------------------------------------------------------
__global__ void softmax_kernel(const float* __restrict__ atr, float* __restrict__ attn) {
    int t = blockIdx.x, b = blockIdx.y;
    int tid = threadIdx.x;  // 256
    __shared__ float red[8];
    const float* g = g_gram + ((size_t)b * Tq + t) * Tq;
    float r0 = g[tid], r1 = g[tid + 256];
    int warp = tid >> 5, lane = tid & 31;

    for (int a = 0; a < Aq; ++a) {
        float s = atr[b * Aq + a];
        float s2 = s * s;
        float v0 = s2 * r0, v1 = s2 * r1;
        float m = fmaxf(v0, v1);
        #pragma unroll
        for (int off = 16; off; off >>= 1) m = fmaxf(m, __shfl_xor_sync(0xffffffffu, m, off));
        if (lane == 0) red[warp] = m;
        __syncthreads();
        float mm = red[0];
        #pragma unroll
        for (int w = 1; w < 8; ++w) mm = fmaxf(mm, red[w]);
        __syncthreads();
        float e0 = __expf(v0 - mm), e1 = __expf(v1 - mm);
        float ssum = e0 + e1;
        #pragma unroll
        for (int off = 16; off; off >>= 1) ssum += __shfl_xor_sync(0xffffffffu, ssum, off);
        if (lane == 0) red[warp] = ssum;
        __syncthreads();
        float tot = red[0];
        #pragma unroll
        for (int w = 1; w < 8; ++w) tot += red[w];
        float inv = 1.0f / tot;
        float* dst = attn + (((size_t)(b * Aq + a) * Tq) + t) * Tq;
        dst[tid] = e0 * inv;
        dst[tid + 256] = e1 * inv;
        __syncthreads();
    }
}

// ---------------------------------------------------------------------------
// Kernel 3: attn_out[ba] = s_ba * (attn_ba @ X_b)
// ---------------------------------------------------------------------------
__global__ __launch_bounds__(256, 1)
void av_kernel(const float* __restrict__ atr, const float* __restrict__ attn) {
    __shared__ Smem s;
    int ba = blockIdx.z;
    int b = ba >> 3;
    const float* Am = attn + (size_t)ba * Tq * Tq;
    const float* Bm = g_xt + (size_t)b * Eq * Tq;
    int m0 = blockIdx.y * BMm, n0 = blockIdx.x * BNm;
    float acc[2][8][4] = {};
    gemm_bf16x3(Am, Tq, m0, Bm, Tq, n0, 0, Tq / BKm, acc, s);

    const int lane = threadIdx.x & 31, wid = threadIdx.x >> 5;
    const int gid = lane >> 2, tig = lane & 3;
    const int mw = (wid >> 1) * 32, nw = (wid & 1) * 64;
    float sc = atr[ba];
    float* Cp = g_attn_out + (size_t)ba * Tq * Eq;
    #pragma unroll
    for (int mt = 0; mt < 2; ++mt) {
        int mr0 = m0 + mw + mt * 16 + gid;
        int mr1 = mr0 + 8;
        #pragma unroll
        for (int nt = 0; nt < 8; ++nt) {
            int col = n0 + nw + nt * 8 + 2 * tig;
            float2 v0 = make_float2(sc * acc[mt][nt][0], sc * acc[mt][nt][1]);
            float2 v1 = make_float2(sc * acc[mt][nt][2], sc * acc[mt][nt][3]);
            *(float2*)&Cp[(size_t)mr0 * Eq + col] = v0;
            *(float2*)&Cp[(size_t)mr1 * Eq + col] = v1;
        }
    }
}

// ---------------------------------------------------------------------------
// Kernel 4a: out = bias (init)
// ---------------------------------------------------------------------------
__global__ void bias_init_kernel(const float* __restrict__ bias, float* __restrict__ out) {
    int idx = blockIdx.x * 256 + threadIdx.x;
    float4 bv = *(const float4*)&bias[(idx & 63) * 4];
    ((float4*)out)[idx] = bv;
}

// ---------------------------------------------------------------------------
// Kernel 4b: out += flat_attn_out(8192x2048) @ W^T(2048x256), split-K=2
// ---------------------------------------------------------------------------
__global__ __launch_bounds__(256, 1)
void proj_kernel(const float* __restrict__ W, float* __restrict__ out) {
    __shared__ Smem s;
    const int Kd = Aq * Eq;   // 2048
    const int KS = Kd / 2;    // 1024 per split
    int m0 = blockIdx.y * BMm, n0 = blockIdx.x * BNm;
    int kBase = blockIdx.z * KS;
    float acc[2][8][4] = {};
    gemm_bf16x3(g_attn_out, Kd, m0, W, Kd, n0, kBase, KS / BKm, acc, s);

    const int lane = threadIdx.x & 31, wid = threadIdx.x >> 5;
    const int gid = lane >> 2, tig = lane & 3;
    const int mw = (wid >> 1) * 32, nw = (wid & 1) * 64;
    #pragma unroll
    for (int mt = 0; mt < 2; ++mt) {
        int mr0 = m0 + mw + mt * 16 + gid;
        int mr1 = mr0 + 8;
        #pragma unroll
        for (int nt = 0; nt < 8; ++nt) {
            int col = n0 + nw + nt * 8 + 2 * tig;
            atomicAdd(&out[(size_t)mr0 * Eq + col],     acc[mt][nt][0]);
            atomicAdd(&out[(size_t)mr0 * Eq + col + 1], acc[mt][nt][1]);
            atomicAdd(&out[(size_t)mr1 * Eq + col],     acc[mt][nt][2]);
            atomicAdd(&out[(size_t)mr1 * Eq + col + 1], acc[mt][nt][3]);
        }
    }
}

// ---------------------------------------------------------------------------
extern "C" void kernel_launch(void* const* d_in, const int* in_sizes, int n_in,
                              void* d_out, int out_size) {
    const float* sent = (const float*)d_in[0];
    const int*   mask = (const int*)d_in[1];
    const float* atr  = (const float*)d_in[2];
    const float* W    = (const float*)d_in[3];
    const float* bias = (const float*)d_in[4];
    float* out = (float*)d_out;

    const long long OUT_E  = (long long)Bq * Tq * Eq;        // 2,097,152
    const long long ATTN_E = (long long)Bq * Aq * Tq * Tq;   // 33,554,432

    float* attn_ptr;
    if ((long long)out_size >= OUT_E + ATTN_E) {
        attn_ptr = out + OUT_E;                  // tuple (output, attn) flattened
    } else {
        void* p = nullptr;
        cudaGetSymbolAddress(&p, g_attn_fb);     // query only, capture-safe
        attn_ptr = (float*)p;
    }

    transpose_kernel<<<dim3(Eq / 32, Tq / 32, Bq), dim3(32, 8)>>>(sent);
    gram_kernel<<<dim3(Tq / BNm, Tq / BMm, Bq), 256>>>(sent, mask);
    softmax_kernel<<<dim3(Tq, Bq), 256>>>(atr, attn_ptr);
    av_kernel<<<dim3(Eq / BNm, Tq / BMm, Bq * Aq), 256>>>(atr, attn_ptr);
    bias_init_kernel<<<(Bq * Tq * Eq / 4) / 256, 256>>>(bias, out);
    proj_kernel<<<dim3(Eq / BNm, (Bq * Tq) / BMm, 2), 256>>>(W, out);
}

// round 6
// speedup vs baseline: 4.0862x; 1.1917x over previous
#include <cuda_runtime.h>
#include <cuda_fp16.h>
#include <cstdint>

// Problem dims
#define Bq 16
#define Tq 512
#define Eq 256
#define Aq 8

// Scratch (allocation-free rules: __device__ globals)
__device__ float  g_gram[Bq * Tq * Tq];             // masked gram fp32
__device__ __half g_xh [Bq * Tq * Eq];              // X hi (B,T,E)
__device__ __half g_xl [Bq * Tq * Eq];              // X lo
__device__ __half g_xth[Bq * Eq * Tq];              // X^T hi (B,E,T)
__device__ __half g_attn_h[Bq * Aq * Tq * Tq];      // attn hi
__device__ __half g_attn_l[Bq * Aq * Tq * Tq];      // attn lo
__device__ __half g_aoh[Bq * Aq * Tq * Eq];         // attn_out hi (B,A,T,E)
__device__ __half g_aol[Bq * Aq * Tq * Eq];         // attn_out lo
__device__ __half g_wh [Eq * Aq * Eq];              // W hi
__device__ float  g_attn_fb[Bq * Aq * Tq * Tq];     // fallback fp32 attn buffer

// GEMM tiling: 128x128 CTA tile, k32 fp-elem stages, 256 threads, 8 warps (4x2)
// smem matrix: 128 rows x 80B (4 x 16B chunks used + 16B pad -> ldmatrix conflict-free)
#define MATB 10240
#define NSTAGE 3

// ---------------------------------------------------------------------------
__device__ __forceinline__ uint32_t smem_u32(const void* p) {
    uint32_t a;
    asm("{ .reg .u64 t; cvta.to.shared.u64 t, %1; cvt.u32.u64 %0, t; }" : "=r"(a) : "l"(p));
    return a;
}
__device__ __forceinline__ void cp16(uint32_t dst, const void* src) {
    asm volatile("cp.async.cg.shared.global [%0], [%1], 16;"
                 :: "r"(dst), "l"(__cvta_generic_to_global(src)));
}
__device__ __forceinline__ void cp_commit() {
    asm volatile("cp.async.commit_group;");
}
template <int N>
__device__ __forceinline__ void cp_wait() {
    asm volatile("cp.async.wait_group %0;" :: "n"(N));
}
__device__ __forceinline__ void ldsm_x4(unsigned& r0, unsigned& r1, unsigned& r2,
                                        unsigned& r3, uint32_t addr) {
    asm volatile("ldmatrix.sync.aligned.m8n8.x4.shared.b16 {%0,%1,%2,%3}, [%4];"
                 : "=r"(r0), "=r"(r1), "=r"(r2), "=r"(r3) : "r"(addr));
}
__device__ __forceinline__ void mma16816(float* c, const unsigned* a, const unsigned* b) {
    asm volatile(
        "mma.sync.aligned.m16n8k16.row.col.f32.f16.f16.f32 "
        "{%0,%1,%2,%3}, {%4,%5,%6,%7}, {%8,%9}, {%0,%1,%2,%3};"
        : "+f"(c[0]), "+f"(c[1]), "+f"(c[2]), "+f"(c[3])
        : "r"(a[0]), "r"(a[1]), "r"(a[2]), "r"(a[3]), "r"(b[0]), "r"(b[1]));
}

// ---------------------------------------------------------------------------
// Mainloop: acc += A(128 x K) * B^T. A split (hi+lo fp16), B hi (+ lo if NPASS==3).
// NPASS==2: ah*bh + al*bh (exact in A, err = a*(b-bh) ~ 2^-11.5)
// NPASS==3: + ah*bl        (err ~ 2^-22)
// cp.async 3-stage pipeline, ldmatrix fragments, 80B-stride conflict-free smem.
// ---------------------------------------------------------------------------
template <int NPASS>
__device__ __forceinline__ void mma_loop(
    const __half* __restrict__ Agh, const __half* __restrict__ Agl, int lda, int m0,
    const __half* __restrict__ Bgh, const __half* __restrict__ Bgl, int ldb, int n0,
    int kIters, char* smb, float acc[2][8][4])
{
    const int STAGE = (NPASS == 3 ? 4 : 3) * MATB;
    const int t = threadIdx.x;
    const int r = t >> 1, cb = (t & 1) * 2;     // loader: row, chunk-pair
    const int lane = t & 31, wid = t >> 5;
    const int mw = (wid >> 1) * 32, nw = (wid & 1) * 64;
    const int lr = lane & 7, q = lane >> 3;
    const int a_ro = (q & 1) * 8 + lr, a_co = (q >> 1);
    const int b_ro = (q >> 1) * 8 + lr, b_co = (q & 1);

    const __half* pa_h = Agh + (size_t)(m0 + r) * lda + cb * 8;
    const __half* pa_l = Agl + (size_t)(m0 + r) * lda + cb * 8;
    const __half* pb_h = Bgh + (size_t)(n0 + r) * ldb + cb * 8;
    const __half* pb_l = (NPASS == 3) ? Bgl + (size_t)(n0 + r) * ldb + cb * 8 : pb_h;

    const uint32_t sbase = smem_u32(smb);
    const uint32_t rowoff = (uint32_t)r * 80u + (uint32_t)cb * 16u;

    auto issue = [&](int it) {
        uint32_t sb = sbase + (uint32_t)((it % NSTAGE) * STAGE) + rowoff;
        int k0 = it * 32;
        #pragma unroll
        for (int j = 0; j < 2; ++j) {
            cp16(sb + j * 16,            pa_h + k0 + j * 8);
            cp16(sb + MATB + j * 16,     pa_l + k0 + j * 8);
            cp16(sb + 2 * MATB + j * 16, pb_h + k0 + j * 8);
            if (NPASS == 3)
                cp16(sb + 3 * MATB + j * 16, pb_l + k0 + j * 8);
        }
    };
    issue(0); cp_commit();
    issue(1); cp_commit();

    for (int it = 0; it < kIters; ++it) {
        cp_wait<1>();
        __syncthreads();
        if (it + 2 < kIters) issue(it + 2);
        cp_commit();
        uint32_t sb = sbase + (uint32_t)((it % NSTAGE) * STAGE);
        #pragma unroll
        for (int ks = 0; ks < 2; ++ks) {
            unsigned ah[2][4], al[2][4];
            #pragma unroll
            for (int mt = 0; mt < 2; ++mt) {
                uint32_t ad = sb + (uint32_t)((mw + mt * 16 + a_ro) * 80 + (2 * ks + a_co) * 16);
                ldsm_x4(ah[mt][0], ah[mt][1], ah[mt][2], ah[mt][3], ad);
                ldsm_x4(al[mt][0], al[mt][1], al[mt][2], al[mt][3], ad + MATB);
            }
            unsigned bh[8][2], bl[8][2];
            #pragma unroll
            for (int np = 0; np < 4; ++np) {
                uint32_t bd = sb + 2 * MATB +
                              (uint32_t)((nw + np * 16 + b_ro) * 80 + (2 * ks + b_co) * 16);
                ldsm_x4(bh[2*np][0], bh[2*np][1], bh[2*np+1][0], bh[2*np+1][1], bd);
                if (NPASS == 3)
                    ldsm_x4(bl[2*np][0], bl[2*np][1], bl[2*np+1][0], bl[2*np+1][1], bd + MATB);
            }
            #pragma unroll
            for (int nt = 0; nt < 8; ++nt)
                #pragma unroll
                for (int mt = 0; mt < 2; ++mt) {
                    mma16816(acc[mt][nt], ah[mt], bh[nt]);
                    mma16816(acc[mt][nt], al[mt], bh[nt]);
                    if (NPASS == 3) mma16816(acc[mt][nt], ah[mt], bl[nt]);
                }
        }
        // no trailing sync: next iteration's wait+sync guards buffer reuse
    }
}

// ---------------------------------------------------------------------------
// Kernel 0a: X -> Xh, Xl (B,T,E) and Xth (B,E,T)
// ---------------------------------------------------------------------------
__global__ void prep_x_kernel(const float* __restrict__ X) {
    __shared__ float tile[32][33];
    int b = blockIdx.z;
    int e0 = blockIdx.x * 32, t0 = blockIdx.y * 32;
    const float* Xb = X + (size_t)b * Tq * Eq;
    int tx = threadIdx.x, ty = threadIdx.y;  // 32x8
    #pragma unroll
    for (int i = 0; i < 32; i += 8) {
        float v = Xb[(size_t)(t0 + ty + i) * Eq + e0 + tx];
        tile[ty + i][tx] = v;
        __half h = __float2half_rn(v);
        __half l = __float2half_rn(v - __half2float(h));
        size_t idx = ((size_t)b * Tq + t0 + ty + i) * Eq + e0 + tx;
        g_xh[idx] = h;
        g_xl[idx] = l;
    }
    __syncthreads();
    #pragma unroll
    for (int i = 0; i < 32; i += 8) {
        float v = tile[tx][ty + i];
        g_xth[((size_t)b * Eq + e0 + ty + i) * Tq + t0 + tx] = __float2half_rn(v);
    }
}

// Kernel 0b: W -> Wh
__global__ void prep_w_kernel(const float* __restrict__ W) {
    int idx = blockIdx.x * 256 + threadIdx.x;   // over 524288
    g_wh[idx] = __float2half_rn(W[idx]);
}

// ---------------------------------------------------------------------------
// Kernel 1: G_b = mask-outer ? (X_b X_b^T)/sqrt(E) : 0   (3-pass fp16, K=256)
// ---------------------------------------------------------------------------
__global__ __launch_bounds__(256, 1)
void gram_kernel(const int* __restrict__ mask) {
    extern __shared__ char smb[];
    int b = blockIdx.z;
    int m0 = blockIdx.y * 128, n0 = blockIdx.x * 128;
    const __half* Xh = g_xh + (size_t)b * Tq * Eq;
    const __half* Xl = g_xl + (size_t)b * Tq * Eq;
    float acc[2][8][4] = {};
    mma_loop<3>(Xh, Xl, Eq, m0, Xh, Xl, Eq, n0, Eq / 32, smb, acc);

    const int lane = threadIdx.x & 31, wid = threadIdx.x >> 5;
    const int gid = lane >> 2, tig = lane & 3;
    const int mw = (wid >> 1) * 32, nw = (wid & 1) * 64;
    const int* mb = mask + b * Tq;
    float* G = g_gram + (size_t)b * Tq * Tq;
    #pragma unroll
    for (int mt = 0; mt < 2; ++mt) {
        int mr0 = m0 + mw + mt * 16 + gid;
        int mr1 = mr0 + 8;
        float s0 = (mb[mr0] != 0) ? 0.0625f : 0.0f;   // 1/sqrt(256), fold row mask
        float s1 = (mb[mr1] != 0) ? 0.0625f : 0.0f;
        #pragma unroll
        for (int nt = 0; nt < 8; ++nt) {
            int col = n0 + nw + nt * 8 + 2 * tig;
            float c0 = (mb[col] != 0) ? 1.0f : 0.0f;
            float c1 = (mb[col + 1] != 0) ? 1.0f : 0.0f;
            *(float2*)&G[(size_t)mr0 * Tq + col] =
                make_float2(acc[mt][nt][0] * s0 * c0, acc[mt][nt][1] * s0 * c1);
            *(float2*)&G[(size_t)mr1 * Tq + col] =
                make_float2(acc[mt][nt][2] * s1 * c0, acc[mt][nt][3] * s1 * c1);
        }
    }
}

// ---------------------------------------------------------------------------
// Kernel 2: softmax over rows of s^2*G; writes fp32 attn + fp16 hi/lo planes
// ---------------------------------------------------------------------------
__global__ void softmax_kernel(const float* __restrict__ atr, float* __restrict__ attn) {
    int t = blockIdx.x, b = blockIdx.y;
    int tid = threadIdx.x;  // 256
    __shared__ float red[8];
    const float* g = g_gram + ((size_t)b * Tq + t) * Tq;
    float r0 = g[tid], r1 = g[tid + 256];
    int warp = tid >> 5, lane = tid & 31;

    for (int a = 0; a < Aq; ++a) {
        float s = atr[b * Aq + a];
        float s2 = s * s;
        float v0 = s2 * r0, v1 = s2 * r1;
        float m = fmaxf(v0, v1);
        #pragma unroll
        for (int off = 16; off; off >>= 1) m = fmaxf(m, __shfl_xor_sync(0xffffffffu, m, off));
        if (lane == 0) red[warp] = m;
        __syncthreads();
        float mm = red[0];
        #pragma unroll
        for (int w = 1; w < 8; ++w) mm = fmaxf(mm, red[w]);
        __syncthreads();
        float e0 = __expf(v0 - mm), e1 = __expf(v1 - mm);
        float ssum = e0 + e1;
        #pragma unroll
        for (int off = 16; off; off >>= 1) ssum += __shfl_xor_sync(0xffffffffu, ssum, off);
        if (lane == 0) red[warp] = ssum;
        __syncthreads();
        float tot = red[0];
        #pragma unroll
        for (int w = 1; w < 8; ++w) tot += red[w];
        float inv = 1.0f / tot;
        float o0 = e0 * inv, o1 = e1 * inv;
        size_t rowbase = (((size_t)(b * Aq + a) * Tq) + t) * Tq;
        attn[rowbase + tid] = o0;
        attn[rowbase + tid + 256] = o1;
        __half h0 = __float2half_rn(o0);
        __half l0 = __float2half_rn(o0 - __half2float(h0));
        __half h1 = __float2half_rn(o1);
        __half l1 = __float2half_rn(o1 - __half2float(h1));
        g_attn_h[rowbase + tid] = h0;
        g_attn_l[rowbase + tid] = l0;
        g_attn_h[rowbase + tid + 256] = h1;
        g_attn_l[rowbase + tid + 256] = l1;
        __syncthreads();
    }
}

// ---------------------------------------------------------------------------
// Kernel 3: attn_out[ba] = s_ba * (attn_ba @ X_b)  (2-pass); writes fp16 hi/lo
// ---------------------------------------------------------------------------
__global__ __launch_bounds__(256, 2)
void av_kernel(const float* __restrict__ atr) {
    extern __shared__ char smb[];
    int ba = blockIdx.z, b = ba >> 3;
    int m0 = blockIdx.y * 128, n0 = blockIdx.x * 128;
    const __half* Ah = g_attn_h + (size_t)ba * Tq * Tq;
    const __half* Al = g_attn_l + (size_t)ba * Tq * Tq;
    const __half* Bh = g_xth + (size_t)b * Eq * Tq;
    float acc[2][8][4] = {};
    mma_loop<2>(Ah, Al, Tq, m0, Bh, nullptr, Tq, n0, Tq / 32, smb, acc);

    const int lane = threadIdx.x & 31, wid = threadIdx.x >> 5;
    const int gid = lane >> 2, tig = lane & 3;
    const int mw = (wid >> 1) * 32, nw = (wid & 1) * 64;
    float sc = atr[ba];
    #pragma unroll
    for (int mt = 0; mt < 2; ++mt) {
        int mr0 = m0 + mw + mt * 16 + gid;
        int mr1 = mr0 + 8;
        #pragma unroll
        for (int nt = 0; nt < 8; ++nt) {
            int col = n0 + nw + nt * 8 + 2 * tig;
            size_t i0 = ((size_t)ba * Tq + mr0) * Eq + col;
            size_t i1 = ((size_t)ba * Tq + mr1) * Eq + col;
            float v0 = sc * acc[mt][nt][0], v1 = sc * acc[mt][nt][1];
            float v2 = sc * acc[mt][nt][2], v3 = sc * acc[mt][nt][3];
            __half h0 = __float2half_rn(v0), h1 = __float2half_rn(v1);
            __half h2 = __float2half_rn(v2), h3 = __float2half_rn(v3);
            __half l0 = __float2half_rn(v0 - __half2float(h0));
            __half l1 = __float2half_rn(v1 - __half2float(h1));
            __half l2 = __float2half_rn(v2 - __half2float(h2));
            __half l3 = __float2half_rn(v3 - __half2float(h3));
            *(__half2*)&g_aoh[i0] = __halves2half2(h0, h1);
            *(__half2*)&g_aol[i0] = __halves2half2(l0, l1);
            *(__half2*)&g_aoh[i1] = __halves2half2(h2, h3);
            *(__half2*)&g_aol[i1] = __halves2half2(l2, l3);
        }
    }
}

// ---------------------------------------------------------------------------
// Kernel 4a: out = bias (init)
// ---------------------------------------------------------------------------
__global__ void bias_init_kernel(const float* __restrict__ bias, float* __restrict__ out) {
    int idx = blockIdx.x * 256 + threadIdx.x;
    float4 bv = *(const float4*)&bias[(idx & 63) * 4];
    ((float4*)out)[idx] = bv;
}

// ---------------------------------------------------------------------------
// Kernel 4b: out += flat_attn_out(8192x2048) @ Wh^T(2048x256), split-K=2 (2-pass)
// ---------------------------------------------------------------------------
__global__ __launch_bounds__(256, 2)
void proj_kernel(float* __restrict__ out) {
    extern __shared__ char smb[];
    const int Kd = Aq * Eq;  // 2048
    const int KS = Kd / 2;
    int m0 = blockIdx.y * 128, n0 = blockIdx.x * 128;
    int kBase = blockIdx.z * KS;
    float acc[2][8][4] = {};
    mma_loop<2>(g_aoh + kBase, g_aol + kBase, Kd, m0,
                g_wh + kBase, nullptr, Kd, n0, KS / 32, smb, acc);

    const int lane = threadIdx.x & 31, wid = threadIdx.x >> 5;
    const int gid = lane >> 2, tig = lane & 3;
    const int mw = (wid >> 1) * 32, nw = (wid & 1) * 64;
    #pragma unroll
    for (int mt = 0; mt < 2; ++mt) {
        int mr0 = m0 + mw + mt * 16 + gid;
        int mr1 = mr0 + 8;
        #pragma unroll
        for (int nt = 0; nt < 8; ++nt) {
            int col = n0 + nw + nt * 8 + 2 * tig;
            atomicAdd(&out[(size_t)mr0 * Eq + col],     acc[mt][nt][0]);
            atomicAdd(&out[(size_t)mr0 * Eq + col + 1], acc[mt][nt][1]);
            atomicAdd(&out[(size_t)mr1 * Eq + col],     acc[mt][nt][2]);
            atomicAdd(&out[(size_t)mr1 * Eq + col + 1], acc[mt][nt][3]);
        }
    }
}

// ---------------------------------------------------------------------------
extern "C" void kernel_launch(void* const* d_in, const int* in_sizes, int n_in,
                              void* d_out, int out_size) {
    const float* sent = (const float*)d_in[0];
    const int*   mask = (const int*)d_in[1];
    const float* atr  = (const float*)d_in[2];
    const float* W    = (const float*)d_in[3];
    const float* bias = (const float*)d_in[4];
    float* out = (float*)d_out;

    const long long OUT_E  = (long long)Bq * Tq * Eq;        // 2,097,152
    const long long ATTN_E = (long long)Bq * Aq * Tq * Tq;   // 33,554,432

    float* attn_ptr;
    if ((long long)out_size >= OUT_E + ATTN_E) {
        attn_ptr = out + OUT_E;                  // tuple (output, attn) flattened
    } else {
        void* p = nullptr;
        cudaGetSymbolAddress(&p, g_attn_fb);     // query only, capture-safe
        attn_ptr = (float*)p;
    }

    const int SM2 = 3 * 3 * MATB;   // 92160 B  (2-pass stages)
    const int SM3 = 3 * 4 * MATB;   // 122880 B (3-pass stages)
    cudaFuncSetAttribute(gram_kernel, cudaFuncAttributeMaxDynamicSharedMemorySize, SM3);
    cudaFuncSetAttribute(av_kernel,   cudaFuncAttributeMaxDynamicSharedMemorySize, SM2);
    cudaFuncSetAttribute(proj_kernel, cudaFuncAttributeMaxDynamicSharedMemorySize, SM2);

    prep_x_kernel<<<dim3(Eq / 32, Tq / 32, Bq), dim3(32, 8)>>>(sent);
    prep_w_kernel<<<(Eq * Aq * Eq) / 256, 256>>>(W);
    gram_kernel<<<dim3(Tq / 128, Tq / 128, Bq), 256, SM3>>>(mask);
    softmax_kernel<<<dim3(Tq, Bq), 256>>>(atr, attn_ptr);
    av_kernel<<<dim3(Eq / 128, Tq / 128, Bq * Aq), 256, SM2>>>(atr);
    bias_init_kernel<<<(Bq * Tq * Eq / 4) / 256, 256>>>(bias, out);
    proj_kernel<<<dim3(Eq / 128, (Bq * Tq) / 128, 2), 256, SM2>>>(out);
}

// round 7
// speedup vs baseline: 4.1815x; 1.0233x over previous
#include <cuda_runtime.h>
#include <cuda_fp16.h>
#include <cstdint>

// Problem dims
#define Bq 16
#define Tq 512
#define Eq 256
#define Aq 8

// Scratch (allocation-free rules: __device__ globals)
__device__ float  g_gram[Bq * Tq * Tq];             // masked gram fp32
__device__ __half g_xh [Bq * Tq * Eq];              // X hi (B,T,E)
__device__ __half g_xl [Bq * Tq * Eq];              // X lo
__device__ __half g_xth[Bq * Eq * Tq];              // X^T hi (B,E,T)
__device__ __half g_aoh[Bq * Aq * Tq * Eq];         // attn_out hi (B,A,T,E)
__device__ __half g_aol[Bq * Aq * Tq * Eq];         // attn_out lo
__device__ __half g_wh [Eq * Aq * Eq];              // W hi
__device__ float  g_attn_fb[Bq * Aq * Tq * Tq];     // fallback fp32 attn buffer

// GEMM tiling: 128x128 CTA tile, k32 fp-elem stages, 256 threads, 8 warps (4x2)
// smem matrix: 128 rows x 80B (4 x 16B chunks + 16B pad -> ldmatrix conflict-free)
#define MATB 10240
#define NSTAGE 3

// ---------------------------------------------------------------------------
__device__ __forceinline__ uint32_t smem_u32(const void* p) {
    uint32_t a;
    asm("{ .reg .u64 t; cvta.to.shared.u64 t, %1; cvt.u32.u64 %0, t; }" : "=r"(a) : "l"(p));
    return a;
}
__device__ __forceinline__ void cp16(uint32_t dst, const void* src) {
    asm volatile("cp.async.cg.shared.global [%0], [%1], 16;"
                 :: "r"(dst), "l"(__cvta_generic_to_global(src)));
}
__device__ __forceinline__ void cp_commit() {
    asm volatile("cp.async.commit_group;");
}
template <int N>
__device__ __forceinline__ void cp_wait() {
    asm volatile("cp.async.wait_group %0;" :: "n"(N));
}
__device__ __forceinline__ void ldsm_x4(unsigned& r0, unsigned& r1, unsigned& r2,
                                        unsigned& r3, uint32_t addr) {
    asm volatile("ldmatrix.sync.aligned.m8n8.x4.shared.b16 {%0,%1,%2,%3}, [%4];"
                 : "=r"(r0), "=r"(r1), "=r"(r2), "=r"(r3) : "r"(addr));
}
__device__ __forceinline__ void mma16816(float* c, const unsigned* a, const unsigned* b) {
    asm volatile(
        "mma.sync.aligned.m16n8k16.row.col.f32.f16.f16.f32 "
        "{%0,%1,%2,%3}, {%4,%5,%6,%7}, {%8,%9}, {%0,%1,%2,%3};"
        : "+f"(c[0]), "+f"(c[1]), "+f"(c[2]), "+f"(c[3])
        : "r"(a[0]), "r"(a[1]), "r"(a[2]), "r"(a[3]), "r"(b[0]), "r"(b[1]));
}

// ---------------------------------------------------------------------------
// MMA compute phase over one k32 stage. Ah/Al at abase/abase+MATB, Bh at bbase
// (+ Bl at bbase+MATB when NPASS==3).
// ---------------------------------------------------------------------------
template <int NPASS>
__device__ __forceinline__ void mma_stage(uint32_t abase, uint32_t bbase,
                                          float acc[2][8][4]) {
    const int lane = threadIdx.x & 31, wid = threadIdx.x >> 5;
    const int mw = (wid >> 1) * 32, nw = (wid & 1) * 64;
    const int lr = lane & 7, q = lane >> 3;
    const int a_ro = (q & 1) * 8 + lr, a_co = (q >> 1);
    const int b_ro = (q >> 1) * 8 + lr, b_co = (q & 1);
    #pragma unroll
    for (int ks = 0; ks < 2; ++ks) {
        unsigned ah[2][4], al[2][4];
        #pragma unroll
        for (int mt = 0; mt < 2; ++mt) {
            uint32_t ad = abase + (uint32_t)((mw + mt * 16 + a_ro) * 80 + (2 * ks + a_co) * 16);
            ldsm_x4(ah[mt][0], ah[mt][1], ah[mt][2], ah[mt][3], ad);
            ldsm_x4(al[mt][0], al[mt][1], al[mt][2], al[mt][3], ad + MATB);
        }
        unsigned bh[8][2], bl[8][2];
        #pragma unroll
        for (int np = 0; np < 4; ++np) {
            uint32_t bd = bbase + (uint32_t)((nw + np * 16 + b_ro) * 80 + (2 * ks + b_co) * 16);
            ldsm_x4(bh[2*np][0], bh[2*np][1], bh[2*np+1][0], bh[2*np+1][1], bd);
            if (NPASS == 3)
                ldsm_x4(bl[2*np][0], bl[2*np][1], bl[2*np+1][0], bl[2*np+1][1], bd + MATB);
        }
        #pragma unroll
        for (int nt = 0; nt < 8; ++nt)
            #pragma unroll
            for (int mt = 0; mt < 2; ++mt) {
                mma16816(acc[mt][nt], ah[mt], bh[nt]);
                mma16816(acc[mt][nt], al[mt], bh[nt]);
                if (NPASS == 3) mma16816(acc[mt][nt], ah[mt], bl[nt]);
            }
    }
}

// ---------------------------------------------------------------------------
// Variant 1: A and B pre-split fp16 planes in gmem, all via cp.async.
// ---------------------------------------------------------------------------
template <int NPASS>
__device__ __forceinline__ void mma_loop(
    const __half* __restrict__ Agh, const __half* __restrict__ Agl, int lda, int m0,
    const __half* __restrict__ Bgh, const __half* __restrict__ Bgl, int ldb, int n0,
    int kIters, char* smb, float acc[2][8][4])
{
    const int STAGE = (NPASS == 3 ? 4 : 3) * MATB;
    const int t = threadIdx.x;
    const int r = t >> 1, cb = (t & 1) * 2;
    const __half* pa_h = Agh + (size_t)(m0 + r) * lda + cb * 8;
    const __half* pa_l = Agl + (size_t)(m0 + r) * lda + cb * 8;
    const __half* pb_h = Bgh + (size_t)(n0 + r) * ldb + cb * 8;
    const __half* pb_l = (NPASS == 3) ? Bgl + (size_t)(n0 + r) * ldb + cb * 8 : pb_h;
    const uint32_t sbase = smem_u32(smb);
    const uint32_t rowoff = (uint32_t)r * 80u + (uint32_t)cb * 16u;

    auto issue = [&](int it) {
        uint32_t sb = sbase + (uint32_t)((it % NSTAGE) * STAGE) + rowoff;
        int k0 = it * 32;
        #pragma unroll
        for (int j = 0; j < 2; ++j) {
            cp16(sb + j * 16,            pa_h + k0 + j * 8);
            cp16(sb + MATB + j * 16,     pa_l + k0 + j * 8);
            cp16(sb + 2 * MATB + j * 16, pb_h + k0 + j * 8);
            if (NPASS == 3)
                cp16(sb + 3 * MATB + j * 16, pb_l + k0 + j * 8);
        }
    };
    issue(0); cp_commit();
    issue(1); cp_commit();

    for (int it = 0; it < kIters; ++it) {
        cp_wait<1>();
        __syncthreads();
        if (it + 2 < kIters) issue(it + 2);
        cp_commit();
        uint32_t sb = sbase + (uint32_t)((it % NSTAGE) * STAGE);
        mma_stage<NPASS>(sb, sb + 2 * MATB, acc);
    }
}

// ---------------------------------------------------------------------------
// Variant 2: A fp32 in gmem -> split hi/lo in-kernel (2-stage reg/STS pipeline),
// B hi fp16 via 3-stage cp.async. 2-pass (A exact, err = a*(b-bh)).
// smem: A stages 2 x 2*MATB, then B stages 3 x MATB.
// ---------------------------------------------------------------------------
__device__ __forceinline__ void mma_loop_af32(
    const float* __restrict__ Ag, int lda, int m0,
    const __half* __restrict__ Bgh, int ldb, int n0,
    int kIters, char* smb, float acc[2][8][4])
{
    const int t = threadIdx.x;
    const int r = t >> 1, cb = (t & 1) * 2;
    const float*  pa = Ag + (size_t)(m0 + r) * lda + cb * 8;
    const __half* pb = Bgh + (size_t)(n0 + r) * ldb + cb * 8;
    const uint32_t sbase = smem_u32(smb);
    const uint32_t bbase0 = sbase + 4 * MATB;
    const uint32_t rowoff = (uint32_t)r * 80u + (uint32_t)cb * 16u;

    auto issueB = [&](int it) {
        uint32_t sb = bbase0 + (uint32_t)((it % NSTAGE) * MATB) + rowoff;
        int k0 = it * 32;
        cp16(sb,      pb + k0);
        cp16(sb + 16, pb + k0 + 8);
    };
    float4 fa[4];
    auto gloadA = [&](int it) {
        const float* p = pa + it * 32;
        #pragma unroll
        for (int q = 0; q < 4; ++q) fa[q] = *(const float4*)(p + 4 * q);
    };
    auto stsA = [&](int it) {
        uint32_t sb = sbase + (uint32_t)((it & 1) * 2 * MATB) + rowoff;
        #pragma unroll
        for (int j = 0; j < 2; ++j) {
            float4 v0 = fa[2 * j], v1 = fa[2 * j + 1];
            __half2 h0 = __float22half2_rn(make_float2(v0.x, v0.y));
            __half2 h1 = __float22half2_rn(make_float2(v0.z, v0.w));
            __half2 h2 = __float22half2_rn(make_float2(v1.x, v1.y));
            __half2 h3 = __float22half2_rn(make_float2(v1.z, v1.w));
            __half2 l0 = __float22half2_rn(
                make_float2(v0.x - __low2float(h0), v0.y - __high2float(h0)));
            __half2 l1 = __float22half2_rn(
                make_float2(v0.z - __low2float(h1), v0.w - __high2float(h1)));
            __half2 l2 = __float22half2_rn(
                make_float2(v1.x - __low2float(h2), v1.y - __high2float(h2)));
            __half2 l3 = __float22half2_rn(
                make_float2(v1.z - __low2float(h3), v1.w - __high2float(h3)));
            asm volatile("st.shared.v4.b32 [%0], {%1,%2,%3,%4};"
                         :: "r"(sb + j * 16),
                            "r"(*(unsigned*)&h0), "r"(*(unsigned*)&h1),
                            "r"(*(unsigned*)&h2), "r"(*(unsigned*)&h3));
            asm volatile("st.shared.v4.b32 [%0], {%1,%2,%3,%4};"
                         :: "r"(sb + MATB + j * 16),
                            "r"(*(unsigned*)&l0), "r"(*(unsigned*)&l1),
                            "r"(*(unsigned*)&l2), "r"(*(unsigned*)&l3));
        }
    };

    issueB(0); cp_commit();
    issueB(1); cp_commit();
    gloadA(0);

    for (int it = 0; it < kIters; ++it) {
        stsA(it);
        cp_wait<1>();
        __syncthreads();
        if (it + 2 < kIters) issueB(it + 2);
        cp_commit();
        if (it + 1 < kIters) gloadA(it + 1);
        uint32_t ab = sbase + (uint32_t)((it & 1) * 2 * MATB);
        uint32_t bb = bbase0 + (uint32_t)((it % NSTAGE) * MATB);
        mma_stage<2>(ab, bb, acc);
    }
}

// ---------------------------------------------------------------------------
// Kernel 0a: X -> Xh, Xl (B,T,E) and Xth (B,E,T)
// ---------------------------------------------------------------------------
__global__ void prep_x_kernel(const float* __restrict__ X) {
    __shared__ float tile[32][33];
    int b = blockIdx.z;
    int e0 = blockIdx.x * 32, t0 = blockIdx.y * 32;
    const float* Xb = X + (size_t)b * Tq * Eq;
    int tx = threadIdx.x, ty = threadIdx.y;  // 32x8
    #pragma unroll
    for (int i = 0; i < 32; i += 8) {
        float v = Xb[(size_t)(t0 + ty + i) * Eq + e0 + tx];
        tile[ty + i][tx] = v;
        __half h = __float2half_rn(v);
        __half l = __float2half_rn(v - __half2float(h));
        size_t idx = ((size_t)b * Tq + t0 + ty + i) * Eq + e0 + tx;
        g_xh[idx] = h;
        g_xl[idx] = l;
    }
    __syncthreads();
    #pragma unroll
    for (int i = 0; i < 32; i += 8) {
        float v = tile[tx][ty + i];
        g_xth[((size_t)b * Eq + e0 + ty + i) * Tq + t0 + tx] = __float2half_rn(v);
    }
}

// Kernel 0b: W -> Wh
__global__ void prep_w_kernel(const float* __restrict__ W) {
    int idx = blockIdx.x * 256 + threadIdx.x;
    g_wh[idx] = __float2half_rn(W[idx]);
}

// ---------------------------------------------------------------------------
// Kernel 1: G_b = mask-outer ? (X_b X_b^T)/sqrt(E) : 0   (3-pass fp16, K=256)
// ---------------------------------------------------------------------------
__global__ __launch_bounds__(256, 1)
void gram_kernel(const int* __restrict__ mask) {
    extern __shared__ char smb[];
    int b = blockIdx.z;
    int m0 = blockIdx.y * 128, n0 = blockIdx.x * 128;
    const __half* Xh = g_xh + (size_t)b * Tq * Eq;
    const __half* Xl = g_xl + (size_t)b * Tq * Eq;
    float acc[2][8][4] = {};
    mma_loop<3>(Xh, Xl, Eq, m0, Xh, Xl, Eq, n0, Eq / 32, smb, acc);

    const int lane = threadIdx.x & 31, wid = threadIdx.x >> 5;
    const int gid = lane >> 2, tig = lane & 3;
    const int mw = (wid >> 1) * 32, nw = (wid & 1) * 64;
    const int* mb = mask + b * Tq;
    float* G = g_gram + (size_t)b * Tq * Tq;
    #pragma unroll
    for (int mt = 0; mt < 2; ++mt) {
        int mr0 = m0 + mw + mt * 16 + gid;
        int mr1 = mr0 + 8;
        float s0 = (mb[mr0] != 0) ? 0.0625f : 0.0f;   // 1/sqrt(256), fold row mask
        float s1 = (mb[mr1] != 0) ? 0.0625f : 0.0f;
        #pragma unroll
        for (int nt = 0; nt < 8; ++nt) {
            int col = n0 + nw + nt * 8 + 2 * tig;
            float c0 = (mb[col] != 0) ? 1.0f : 0.0f;
            float c1 = (mb[col + 1] != 0) ? 1.0f : 0.0f;
            *(float2*)&G[(size_t)mr0 * Tq + col] =
                make_float2(acc[mt][nt][0] * s0 * c0, acc[mt][nt][1] * s0 * c1);
            *(float2*)&G[(size_t)mr1 * Tq + col] =
                make_float2(acc[mt][nt][2] * s1 * c0, acc[mt][nt][3] * s1 * c1);
        }
    }
}

// ---------------------------------------------------------------------------
// Kernel 2: softmax over rows of s^2*G; writes ONLY the fp32 attn output
// ---------------------------------------------------------------------------
__global__ void softmax_kernel(const float* __restrict__ atr, float* __restrict__ attn) {
    int t = blockIdx.x, b = blockIdx.y;
    int tid = threadIdx.x;  // 256
    __shared__ float red[8];
    const float* g = g_gram + ((size_t)b * Tq + t) * Tq;
    float r0 = g[tid], r1 = g[tid + 256];
    int warp = tid >> 5, lane = tid & 31;

    for (int a = 0; a < Aq; ++a) {
        float s = atr[b * Aq + a];
        float s2 = s * s;
        float v0 = s2 * r0, v1 = s2 * r1;
        float m = fmaxf(v0, v1);
        #pragma unroll
        for (int off = 16; off; off >>= 1) m = fmaxf(m, __shfl_xor_sync(0xffffffffu, m, off));
        if (lane == 0) red[warp] = m;
        __syncthreads();
        float mm = red[0];
        #pragma unroll
        for (int w = 1; w < 8; ++w) mm = fmaxf(mm, red[w]);
        __syncthreads();
        float e0 = __expf(v0 - mm), e1 = __expf(v1 - mm);
        float ssum = e0 + e1;
        #pragma unroll
        for (int off = 16; off; off >>= 1) ssum += __shfl_xor_sync(0xffffffffu, ssum, off);
        if (lane == 0) red[warp] = ssum;
        __syncthreads();
        float tot = red[0];
        #pragma unroll
        for (int w = 1; w < 8; ++w) tot += red[w];
        float inv = 1.0f / tot;
        size_t rowbase = (((size_t)(b * Aq + a) * Tq) + t) * Tq;
        attn[rowbase + tid] = e0 * inv;
        attn[rowbase + tid + 256] = e1 * inv;
        __syncthreads();
    }
}

// ---------------------------------------------------------------------------
// Kernel 3: attn_out[ba] = s_ba * (attn_ba @ X_b); A = fp32 attn split in-kernel
// ---------------------------------------------------------------------------
__global__ __launch_bounds__(256, 2)
void av_kernel(const float* __restrict__ atr, const float* __restrict__ attn) {
    extern __shared__ char smb[];
    int ba = blockIdx.z, b = ba >> 3;
    int m0 = blockIdx.y * 128, n0 = blockIdx.x * 128;
    const float* Am = attn + (size_t)ba * Tq * Tq;
    const __half* Bh = g_xth + (size_t)b * Eq * Tq;
    float acc[2][8][4] = {};
    mma_loop_af32(Am, Tq, m0, Bh, Tq, n0, Tq / 32, smb, acc);

    const int lane = threadIdx.x & 31, wid = threadIdx.x >> 5;
    const int gid = lane >> 2, tig = lane & 3;
    const int mw = (wid >> 1) * 32, nw = (wid & 1) * 64;
    float sc = atr[ba];
    #pragma unroll
    for (int mt = 0; mt < 2; ++mt) {
        int mr0 = m0 + mw + mt * 16 + gid;
        int mr1 = mr0 + 8;
        #pragma unroll
        for (int nt = 0; nt < 8; ++nt) {
            int col = n0 + nw + nt * 8 + 2 * tig;
            size_t i0 = ((size_t)ba * Tq + mr0) * Eq + col;
            size_t i1 = ((size_t)ba * Tq + mr1) * Eq + col;
            float v0 = sc * acc[mt][nt][0], v1 = sc * acc[mt][nt][1];
            float v2 = sc * acc[mt][nt][2], v3 = sc * acc[mt][nt][3];
            __half h0 = __float2half_rn(v0), h1 = __float2half_rn(v1);
            __half h2 = __float2half_rn(v2), h3 = __float2half_rn(v3);
            __half l0 = __float2half_rn(v0 - __half2float(h0));
            __half l1 = __float2half_rn(v1 - __half2float(h1));
            __half l2 = __float2half_rn(v2 - __half2float(h2));
            __half l3 = __float2half_rn(v3 - __half2float(h3));
            *(__half2*)&g_aoh[i0] = __halves2half2(h0, h1);
            *(__half2*)&g_aol[i0] = __halves2half2(l0, l1);
            *(__half2*)&g_aoh[i1] = __halves2half2(h2, h3);
            *(__half2*)&g_aol[i1] = __halves2half2(l2, l3);
        }
    }
}

// ---------------------------------------------------------------------------
// Kernel 4: out = flat_attn_out(8192x2048) @ Wh^T(2048x256) + bias (full K)
// ---------------------------------------------------------------------------
__global__ __launch_bounds__(256, 2)
void proj_kernel(const float* __restrict__ bias, float* __restrict__ out) {
    extern __shared__ char smb[];
    const int Kd = Aq * Eq;  // 2048
    int m0 = blockIdx.y * 128, n0 = blockIdx.x * 128;
    float acc[2][8][4] = {};
    mma_loop<2>(g_aoh, g_aol, Kd, m0, g_wh, nullptr, Kd, n0, Kd / 32, smb, acc);

    const int lane = threadIdx.x & 31, wid = threadIdx.x >> 5;
    const int gid = lane >> 2, tig = lane & 3;
    const int mw = (wid >> 1) * 32, nw = (wid & 1) * 64;
    #pragma unroll
    for (int mt = 0; mt < 2; ++mt) {
        int mr0 = m0 + mw + mt * 16 + gid;
        int mr1 = mr0 + 8;
        #pragma unroll
        for (int nt = 0; nt < 8; ++nt) {
            int col = n0 + nw + nt * 8 + 2 * tig;
            float b0 = bias[col], b1 = bias[col + 1];
            *(float2*)&out[(size_t)mr0 * Eq + col] =
                make_float2(acc[mt][nt][0] + b0, acc[mt][nt][1] + b1);
            *(float2*)&out[(size_t)mr1 * Eq + col] =
                make_float2(acc[mt][nt][2] + b0, acc[mt][nt][3] + b1);
        }
    }
}

// ---------------------------------------------------------------------------
extern "C" void kernel_launch(void* const* d_in, const int* in_sizes, int n_in,
                              void* d_out, int out_size) {
    const float* sent = (const float*)d_in[0];
    const int*   mask = (const int*)d_in[1];
    const float* atr  = (const float*)d_in[2];
    const float* W    = (const float*)d_in[3];
    const float* bias = (const float*)d_in[4];
    float* out = (float*)d_out;

    const long long OUT_E  = (long long)Bq * Tq * Eq;        // 2,097,152
    const long long ATTN_E = (long long)Bq * Aq * Tq * Tq;   // 33,554,432

    float* attn_ptr;
    if ((long long)out_size >= OUT_E + ATTN_E) {
        attn_ptr = out + OUT_E;                  // tuple (output, attn) flattened
    } else {
        void* p = nullptr;
        cudaGetSymbolAddress(&p, g_attn_fb);     // query only, capture-safe
        attn_ptr = (float*)p;
    }

    const int SM2  = 3 * 3 * MATB;   // 92160  (pre-split 2-pass: 3 stages x 3 mats)
    const int SM3  = 3 * 4 * MATB;   // 122880 (3-pass: 3 stages x 4 mats)
    const int SMAV = 7 * MATB;       // 71680  (A 2x(hi+lo) + B 3 stages)
    cudaFuncSetAttribute(gram_kernel, cudaFuncAttributeMaxDynamicSharedMemorySize, SM3);
    cudaFuncSetAttribute(av_kernel,   cudaFuncAttributeMaxDynamicSharedMemorySize, SMAV);
    cudaFuncSetAttribute(proj_kernel, cudaFuncAttributeMaxDynamicSharedMemorySize, SM2);

    prep_x_kernel<<<dim3(Eq / 32, Tq / 32, Bq), dim3(32, 8)>>>(sent);
    prep_w_kernel<<<(Eq * Aq * Eq) / 256, 256>>>(W);
    gram_kernel<<<dim3(Tq / 128, Tq / 128, Bq), 256, SM3>>>(mask);
    softmax_kernel<<<dim3(Tq, Bq), 256>>>(atr, attn_ptr);
    av_kernel<<<dim3(Eq / 128, Tq / 128, Bq * Aq), 256, SMAV>>>(atr, attn_ptr);
    proj_kernel<<<dim3(Eq / 128, (Bq * Tq) / 128, 1), 256, SM2>>>(bias, out);
}

// round 8
// speedup vs baseline: 6.1181x; 1.4631x over previous
#include <cuda_runtime.h>
#include <cuda_fp16.h>
#include <cstdint>

// Problem dims
#define Bq 16
#define Tq 512
#define Eq 256
#define Aq 8

// Scratch (allocation-free rules: __device__ globals)
__device__ float  g_gram[Bq * Tq * Tq];             // masked gram fp32
__device__ __half g_xh [Bq * Tq * Eq];              // X hi (B,T,E)
__device__ __half g_xl [Bq * Tq * Eq];              // X lo (gram 3-pass only)
__device__ __half g_xth[Bq * Eq * Tq];              // X^T hi (B,E,T)
__device__ __half g_aoh[Bq * Aq * Tq * Eq];         // attn_out hi (B,A,T,E)
__device__ __half g_wh [Eq * Aq * Eq];              // W hi
__device__ float  g_attn_fb[Bq * Aq * Tq * Tq];     // fallback fp32 attn buffer

// GEMM tiling: 128x128 CTA tile, k32 fp-elem stages, 256 threads, 8 warps (4x2)
// smem matrix: 128 rows x 80B (4 x 16B chunks + 16B pad -> ldmatrix conflict-free)
#define MATB 10240
#define NSTAGE 3

// ---------------------------------------------------------------------------
__device__ __forceinline__ uint32_t smem_u32(const void* p) {
    uint32_t a;
    asm("{ .reg .u64 t; cvta.to.shared.u64 t, %1; cvt.u32.u64 %0, t; }" : "=r"(a) : "l"(p));
    return a;
}
__device__ __forceinline__ void cp16(uint32_t dst, const void* src) {
    asm volatile("cp.async.cg.shared.global [%0], [%1], 16;"
                 :: "r"(dst), "l"(__cvta_generic_to_global(src)));
}
__device__ __forceinline__ void cp_commit() {
    asm volatile("cp.async.commit_group;");
}
template <int N>
__device__ __forceinline__ void cp_wait() {
    asm volatile("cp.async.wait_group %0;" :: "n"(N));
}
__device__ __forceinline__ void ldsm_x4(unsigned& r0, unsigned& r1, unsigned& r2,
                                        unsigned& r3, uint32_t addr) {
    asm volatile("ldmatrix.sync.aligned.m8n8.x4.shared.b16 {%0,%1,%2,%3}, [%4];"
                 : "=r"(r0), "=r"(r1), "=r"(r2), "=r"(r3) : "r"(addr));
}
__device__ __forceinline__ void mma16816(float* c, const unsigned* a, const unsigned* b) {
    asm volatile(
        "mma.sync.aligned.m16n8k16.row.col.f32.f16.f16.f32 "
        "{%0,%1,%2,%3}, {%4,%5,%6,%7}, {%8,%9}, {%0,%1,%2,%3};"
        : "+f"(c[0]), "+f"(c[1]), "+f"(c[2]), "+f"(c[3])
        : "r"(a[0]), "r"(a[1]), "r"(a[2]), "r"(a[3]), "r"(b[0]), "r"(b[1]));
}

// ---------------------------------------------------------------------------
// MMA compute over one k32 stage.
// NPASS==1: ah*bh only.        A at abase,       B at bbase.
// NPASS==3: + al*bh + ah*bl.   Al at abase+MATB, Bl at bbase+MATB.
// ---------------------------------------------------------------------------
template <int NPASS>
__device__ __forceinline__ void mma_stage(uint32_t abase, uint32_t bbase,
                                          float acc[2][8][4]) {
    const int lane = threadIdx.x & 31, wid = threadIdx.x >> 5;
    const int mw = (wid >> 1) * 32, nw = (wid & 1) * 64;
    const int lr = lane & 7, q = lane >> 3;
    const int a_ro = (q & 1) * 8 + lr, a_co = (q >> 1);
    const int b_ro = (q >> 1) * 8 + lr, b_co = (q & 1);
    #pragma unroll
    for (int ks = 0; ks < 2; ++ks) {
        unsigned ah[2][4], al[2][4];
        #pragma unroll
        for (int mt = 0; mt < 2; ++mt) {
            uint32_t ad = abase + (uint32_t)((mw + mt * 16 + a_ro) * 80 + (2 * ks + a_co) * 16);
            ldsm_x4(ah[mt][0], ah[mt][1], ah[mt][2], ah[mt][3], ad);
            if (NPASS == 3)
                ldsm_x4(al[mt][0], al[mt][1], al[mt][2], al[mt][3], ad + MATB);
        }
        unsigned bh[8][2], bl[8][2];
        #pragma unroll
        for (int np = 0; np < 4; ++np) {
            uint32_t bd = bbase + (uint32_t)((nw + np * 16 + b_ro) * 80 + (2 * ks + b_co) * 16);
            ldsm_x4(bh[2*np][0], bh[2*np][1], bh[2*np+1][0], bh[2*np+1][1], bd);
            if (NPASS == 3)
                ldsm_x4(bl[2*np][0], bl[2*np][1], bl[2*np+1][0], bl[2*np+1][1], bd + MATB);
        }
        #pragma unroll
        for (int nt = 0; nt < 8; ++nt)
            #pragma unroll
            for (int mt = 0; mt < 2; ++mt) {
                mma16816(acc[mt][nt], ah[mt], bh[nt]);
                if (NPASS == 3) {
                    mma16816(acc[mt][nt], al[mt], bh[nt]);
                    mma16816(acc[mt][nt], ah[mt], bl[nt]);
                }
            }
    }
}

// ---------------------------------------------------------------------------
// Variant 1: pre-split fp16 planes in gmem, all via cp.async.
// NPASS==1: stage = {Ah, Bh};  NPASS==3: stage = {Ah, Al, Bh, Bl}.
// ---------------------------------------------------------------------------
template <int NPASS>
__device__ __forceinline__ void mma_loop(
    const __half* __restrict__ Agh, const __half* __restrict__ Agl, int lda, int m0,
    const __half* __restrict__ Bgh, const __half* __restrict__ Bgl, int ldb, int n0,
    int kIters, char* smb, float acc[2][8][4])
{
    const int BOFF = (NPASS == 3 ? 2 : 1) * MATB;
    const int STAGE = (NPASS == 3 ? 4 : 2) * MATB;
    const int t = threadIdx.x;
    const int r = t >> 1, cb = (t & 1) * 2;
    const __half* pa_h = Agh + (size_t)(m0 + r) * lda + cb * 8;
    const __half* pa_l = (NPASS == 3) ? Agl + (size_t)(m0 + r) * lda + cb * 8 : pa_h;
    const __half* pb_h = Bgh + (size_t)(n0 + r) * ldb + cb * 8;
    const __half* pb_l = (NPASS == 3) ? Bgl + (size_t)(n0 + r) * ldb + cb * 8 : pb_h;
    const uint32_t sbase = smem_u32(smb);
    const uint32_t rowoff = (uint32_t)r * 80u + (uint32_t)cb * 16u;

    auto issue = [&](int it) {
        uint32_t sb = sbase + (uint32_t)((it % NSTAGE) * STAGE) + rowoff;
        int k0 = it * 32;
        #pragma unroll
        for (int j = 0; j < 2; ++j) {
            cp16(sb + j * 16,        pa_h + k0 + j * 8);
            cp16(sb + BOFF + j * 16, pb_h + k0 + j * 8);
            if (NPASS == 3) {
                cp16(sb + MATB + j * 16,     pa_l + k0 + j * 8);
                cp16(sb + 3 * MATB + j * 16, pb_l + k0 + j * 8);
            }
        }
    };
    issue(0); cp_commit();
    issue(1); cp_commit();

    for (int it = 0; it < kIters; ++it) {
        cp_wait<1>();
        __syncthreads();
        if (it + 2 < kIters) issue(it + 2);
        cp_commit();
        uint32_t sb = sbase + (uint32_t)((it % NSTAGE) * STAGE);
        mma_stage<NPASS>(sb, sb + BOFF, acc);
    }
}

// ---------------------------------------------------------------------------
// Variant 2 (av): A fp32 in gmem -> fp16 hi in-kernel (2-stage reg/STS),
// B hi via 3-stage cp.async. Single pass ah*bh.
// smem: A 2 x MATB, then B 3 x MATB  (5 x MATB total).
// ---------------------------------------------------------------------------
__device__ __forceinline__ void mma_loop_af32(
    const float* __restrict__ Ag, int lda, int m0,
    const __half* __restrict__ Bgh, int ldb, int n0,
    int kIters, char* smb, float acc[2][8][4])
{
    const int t = threadIdx.x;
    const int r = t >> 1, cb = (t & 1) * 2;
    const float*  pa = Ag + (size_t)(m0 + r) * lda + cb * 8;
    const __half* pb = Bgh + (size_t)(n0 + r) * ldb + cb * 8;
    const uint32_t sbase = smem_u32(smb);
    const uint32_t bbase0 = sbase + 2 * MATB;
    const uint32_t rowoff = (uint32_t)r * 80u + (uint32_t)cb * 16u;

    auto issueB = [&](int it) {
        uint32_t sb = bbase0 + (uint32_t)((it % NSTAGE) * MATB) + rowoff;
        int k0 = it * 32;
        cp16(sb,      pb + k0);
        cp16(sb + 16, pb + k0 + 8);
    };
    float4 fa[4];
    auto gloadA = [&](int it) {
        const float* p = pa + it * 32;
        #pragma unroll
        for (int q = 0; q < 4; ++q) fa[q] = *(const float4*)(p + 4 * q);
    };
    auto stsA = [&](int it) {
        uint32_t sb = sbase + (uint32_t)((it & 1) * MATB) + rowoff;
        #pragma unroll
        for (int j = 0; j < 2; ++j) {
            float4 v0 = fa[2 * j], v1 = fa[2 * j + 1];
            __half2 h0 = __float22half2_rn(make_float2(v0.x, v0.y));
            __half2 h1 = __float22half2_rn(make_float2(v0.z, v0.w));
            __half2 h2 = __float22half2_rn(make_float2(v1.x, v1.y));
            __half2 h3 = __float22half2_rn(make_float2(v1.z, v1.w));
            asm volatile("st.shared.v4.b32 [%0], {%1,%2,%3,%4};"
                         :: "r"(sb + j * 16),
                            "r"(*(unsigned*)&h0), "r"(*(unsigned*)&h1),
                            "r"(*(unsigned*)&h2), "r"(*(unsigned*)&h3));
        }
    };

    issueB(0); cp_commit();
    issueB(1); cp_commit();
    gloadA(0);

    for (int it = 0; it < kIters; ++it) {
        stsA(it);
        cp_wait<1>();
        __syncthreads();
        if (it + 2 < kIters) issueB(it + 2);
        cp_commit();
        if (it + 1 < kIters) gloadA(it + 1);
        uint32_t ab = sbase + (uint32_t)((it & 1) * MATB);
        uint32_t bb = bbase0 + (uint32_t)((it % NSTAGE) * MATB);
        mma_stage<1>(ab, bb, acc);
    }
}

// ---------------------------------------------------------------------------
// Kernel 0a: X -> Xh, Xl (B,T,E) and Xth (B,E,T)
// ---------------------------------------------------------------------------
__global__ void prep_x_kernel(const float* __restrict__ X) {
    __shared__ float tile[32][33];
    int b = blockIdx.z;
    int e0 = blockIdx.x * 32, t0 = blockIdx.y * 32;
    const float* Xb = X + (size_t)b * Tq * Eq;
    int tx = threadIdx.x, ty = threadIdx.y;  // 32x8
    #pragma unroll
    for (int i = 0; i < 32; i += 8) {
        float v = Xb[(size_t)(t0 + ty + i) * Eq + e0 + tx];
        tile[ty + i][tx] = v;
        __half h = __float2half_rn(v);
        __half l = __float2half_rn(v - __half2float(h));
        size_t idx = ((size_t)b * Tq + t0 + ty + i) * Eq + e0 + tx;
        g_xh[idx] = h;
        g_xl[idx] = l;
    }
    __syncthreads();
    #pragma unroll
    for (int i = 0; i < 32; i += 8) {
        float v = tile[tx][ty + i];
        g_xth[((size_t)b * Eq + e0 + ty + i) * Tq + t0 + tx] = __float2half_rn(v);
    }
}

// Kernel 0b: W -> Wh
__global__ void prep_w_kernel(const float* __restrict__ W) {
    int idx = blockIdx.x * 256 + threadIdx.x;
    g_wh[idx] = __float2half_rn(W[idx]);
}

// ---------------------------------------------------------------------------
// Kernel 1: G_b = mask-outer ? (X_b X_b^T)/sqrt(E) : 0   (3-pass fp16, K=256)
// ---------------------------------------------------------------------------
__global__ __launch_bounds__(256, 1)
void gram_kernel(const int* __restrict__ mask) {
    extern __shared__ char smb[];
    int b = blockIdx.z;
    int m0 = blockIdx.y * 128, n0 = blockIdx.x * 128;
    const __half* Xh = g_xh + (size_t)b * Tq * Eq;
    const __half* Xl = g_xl + (size_t)b * Tq * Eq;
    float acc[2][8][4] = {};
    mma_loop<3>(Xh, Xl, Eq, m0, Xh, Xl, Eq, n0, Eq / 32, smb, acc);

    const int lane = threadIdx.x & 31, wid = threadIdx.x >> 5;
    const int gid = lane >> 2, tig = lane & 3;
    const int mw = (wid >> 1) * 32, nw = (wid & 1) * 64;
    const int* mb = mask + b * Tq;
    float* G = g_gram + (size_t)b * Tq * Tq;
    #pragma unroll
    for (int mt = 0; mt < 2; ++mt) {
        int mr0 = m0 + mw + mt * 16 + gid;
        int mr1 = mr0 + 8;
        float s0 = (mb[mr0] != 0) ? 0.0625f : 0.0f;   // 1/sqrt(256), fold row mask
        float s1 = (mb[mr1] != 0) ? 0.0625f : 0.0f;
        #pragma unroll
        for (int nt = 0; nt < 8; ++nt) {
            int col = n0 + nw + nt * 8 + 2 * tig;
            float c0 = (mb[col] != 0) ? 1.0f : 0.0f;
            float c1 = (mb[col + 1] != 0) ? 1.0f : 0.0f;
            *(float2*)&G[(size_t)mr0 * Tq + col] =
                make_float2(acc[mt][nt][0] * s0 * c0, acc[mt][nt][1] * s0 * c1);
            *(float2*)&G[(size_t)mr1 * Tq + col] =
                make_float2(acc[mt][nt][2] * s1 * c0, acc[mt][nt][3] * s1 * c1);
        }
    }
}

// ---------------------------------------------------------------------------
// Kernel 2: softmax over rows of s^2*G. Row max hoisted out of the attribute
// loop (s^2 >= 0 => max(s^2 g) = s^2 max(g)). Writes only the fp32 attn output.
// ---------------------------------------------------------------------------
__global__ void softmax_kernel(const float* __restrict__ atr, float* __restrict__ attn) {
    int t = blockIdx.x, b = blockIdx.y;
    int tid = threadIdx.x;  // 256
    __shared__ float red[8];
    const float* g = g_gram + ((size_t)b * Tq + t) * Tq;
    float r0 = g[tid], r1 = g[tid + 256];
    int warp = tid >> 5, lane = tid & 31;

    // one-time row max of g
    float m = fmaxf(r0, r1);
    #pragma unroll
    for (int off = 16; off; off >>= 1) m = fmaxf(m, __shfl_xor_sync(0xffffffffu, m, off));
    if (lane == 0) red[warp] = m;
    __syncthreads();
    float mg = red[0];
    #pragma unroll
    for (int w = 1; w < 8; ++w) mg = fmaxf(mg, red[w]);
    __syncthreads();

    for (int a = 0; a < Aq; ++a) {
        float s = atr[b * Aq + a];
        float s2 = s * s;
        float e0 = __expf(s2 * (r0 - mg)), e1 = __expf(s2 * (r1 - mg));
        float ssum = e0 + e1;
        #pragma unroll
        for (int off = 16; off; off >>= 1) ssum += __shfl_xor_sync(0xffffffffu, ssum, off);
        if (lane == 0) red[warp] = ssum;
        __syncthreads();
        float tot = red[0];
        #pragma unroll
        for (int w = 1; w < 8; ++w) tot += red[w];
        float inv = 1.0f / tot;
        size_t rowbase = (((size_t)(b * Aq + a) * Tq) + t) * Tq;
        attn[rowbase + tid] = e0 * inv;
        attn[rowbase + tid + 256] = e1 * inv;
        __syncthreads();
    }
}

// ---------------------------------------------------------------------------
// Kernel 3: attn_out[ba] = s_ba * (attn_ba @ X_b); single-pass, hi plane out
// ---------------------------------------------------------------------------
__global__ __launch_bounds__(256, 2)
void av_kernel(const float* __restrict__ atr, const float* __restrict__ attn) {
    extern __shared__ char smb[];
    int ba = blockIdx.z, b = ba >> 3;
    int m0 = blockIdx.y * 128, n0 = blockIdx.x * 128;
    const float* Am = attn + (size_t)ba * Tq * Tq;
    const __half* Bh = g_xth + (size_t)b * Eq * Tq;
    float acc[2][8][4] = {};
    mma_loop_af32(Am, Tq, m0, Bh, Tq, n0, Tq / 32, smb, acc);

    const int lane = threadIdx.x & 31, wid = threadIdx.x >> 5;
    const int gid = lane >> 2, tig = lane & 3;
    const int mw = (wid >> 1) * 32, nw = (wid & 1) * 64;
    float sc = atr[ba];
    #pragma unroll
    for (int mt = 0; mt < 2; ++mt) {
        int mr0 = m0 + mw + mt * 16 + gid;
        int mr1 = mr0 + 8;
        #pragma unroll
        for (int nt = 0; nt < 8; ++nt) {
            int col = n0 + nw + nt * 8 + 2 * tig;
            size_t i0 = ((size_t)ba * Tq + mr0) * Eq + col;
            size_t i1 = ((size_t)ba * Tq + mr1) * Eq + col;
            *(__half2*)&g_aoh[i0] = __float22half2_rn(
                make_float2(sc * acc[mt][nt][0], sc * acc[mt][nt][1]));
            *(__half2*)&g_aoh[i1] = __float22half2_rn(
                make_float2(sc * acc[mt][nt][2], sc * acc[mt][nt][3]));
        }
    }
}

// ---------------------------------------------------------------------------
// Kernel 4: out = aoh(8192x2048) @ Wh^T(2048x256) + bias (full K, 1-pass)
// ---------------------------------------------------------------------------
__global__ __launch_bounds__(256, 2)
void proj_kernel(const float* __restrict__ bias, float* __restrict__ out) {
    extern __shared__ char smb[];
    const int Kd = Aq * Eq;  // 2048
    int m0 = blockIdx.y * 128, n0 = blockIdx.x * 128;
    float acc[2][8][4] = {};
    mma_loop<1>(g_aoh, nullptr, Kd, m0, g_wh, nullptr, Kd, n0, Kd / 32, smb, acc);

    const int lane = threadIdx.x & 31, wid = threadIdx.x >> 5;
    const int gid = lane >> 2, tig = lane & 3;
    const int mw = (wid >> 1) * 32, nw = (wid & 1) * 64;
    #pragma unroll
    for (int mt = 0; mt < 2; ++mt) {
        int mr0 = m0 + mw + mt * 16 + gid;
        int mr1 = mr0 + 8;
        #pragma unroll
        for (int nt = 0; nt < 8; ++nt) {
            int col = n0 + nw + nt * 8 + 2 * tig;
            float b0 = bias[col], b1 = bias[col + 1];
            *(float2*)&out[(size_t)mr0 * Eq + col] =
                make_float2(acc[mt][nt][0] + b0, acc[mt][nt][1] + b1);
            *(float2*)&out[(size_t)mr1 * Eq + col] =
                make_float2(acc[mt][nt][2] + b0, acc[mt][nt][3] + b1);
        }
    }
}

// ---------------------------------------------------------------------------
extern "C" void kernel_launch(void* const* d_in, const int* in_sizes, int n_in,
                              void* d_out, int out_size) {
    const float* sent = (const float*)d_in[0];
    const int*   mask = (const int*)d_in[1];
    const float* atr  = (const float*)d_in[2];
    const float* W    = (const float*)d_in[3];
    const float* bias = (const float*)d_in[4];
    float* out = (float*)d_out;

    const long long OUT_E  = (long long)Bq * Tq * Eq;        // 2,097,152
    const long long ATTN_E = (long long)Bq * Aq * Tq * Tq;   // 33,554,432

    float* attn_ptr;
    if ((long long)out_size >= OUT_E + ATTN_E) {
        attn_ptr = out + OUT_E;                  // tuple (output, attn) flattened
    } else {
        void* p = nullptr;
        cudaGetSymbolAddress(&p, g_attn_fb);     // query only, capture-safe
        attn_ptr = (float*)p;
    }

    const int SM3  = 3 * 4 * MATB;   // 122880 (gram 3-pass: 3 stages x 4 mats)
    const int SM1  = 3 * 2 * MATB;   // 61440  (proj 1-pass: 3 stages x 2 mats)
    const int SMAV = 5 * MATB;       // 51200  (av: A 2 + B 3)
    cudaFuncSetAttribute(gram_kernel, cudaFuncAttributeMaxDynamicSharedMemorySize, SM3);
    cudaFuncSetAttribute(av_kernel,   cudaFuncAttributeMaxDynamicSharedMemorySize, SMAV);
    cudaFuncSetAttribute(proj_kernel, cudaFuncAttributeMaxDynamicSharedMemorySize, SM1);

    prep_x_kernel<<<dim3(Eq / 32, Tq / 32, Bq), dim3(32, 8)>>>(sent);
    prep_w_kernel<<<(Eq * Aq * Eq) / 256, 256>>>(W);
    gram_kernel<<<dim3(Tq / 128, Tq / 128, Bq), 256, SM3>>>(mask);
    softmax_kernel<<<dim3(Tq, Bq), 256>>>(atr, attn_ptr);
    av_kernel<<<dim3(Eq / 128, Tq / 128, Bq * Aq), 256, SMAV>>>(atr, attn_ptr);
    proj_kernel<<<dim3(Eq / 128, (Bq * Tq) / 128, 1), 256, SM1>>>(bias, out);
}

// round 13
// speedup vs baseline: 6.9011x; 1.1280x over previous
#include <cuda_runtime.h>
#include <cuda_fp16.h>
#include <cstdint>

// Problem dims
#define Bq 16
#define Tq 512
#define Eq 256
#define Aq 8

// Scratch (allocation-free rules: __device__ globals)
__device__ float  g_gram[Bq * Tq * Tq];             // masked gram fp32
__device__ __half g_xh [Bq * Tq * Eq];              // X hi (B,T,E)
__device__ __half g_xl [Bq * Tq * Eq];              // X lo (gram 3-pass only)
__device__ __half g_xth[Bq * Eq * Tq];              // X^T hi (B,E,T)
__device__ __half g_attn_h[Bq * Aq * Tq * Tq];      // attn hi fp16 (av A operand)
__device__ __half g_aoh[Bq * Aq * Tq * Eq];         // attn_out hi (B,A,T,E)
__device__ __half g_wh [Eq * Aq * Eq];              // W hi
__device__ float  g_attn_fb[Bq * Aq * Tq * Tq];     // fallback fp32 attn buffer

// GEMM tiling: 128x128 CTA tile, k32 fp-elem stages, 256 threads, 8 warps (4x2)
// smem matrix: 128 rows x 80B (4 x 16B chunks + 16B pad -> ldmatrix conflict-free)
#define MATB 10240
#define NSTAGE 3

// ---------------------------------------------------------------------------
__device__ __forceinline__ uint32_t smem_u32(const void* p) {
    uint32_t a;
    asm("{ .reg .u64 t; cvta.to.shared.u64 t, %1; cvt.u32.u64 %0, t; }" : "=r"(a) : "l"(p));
    return a;
}
__device__ __forceinline__ void cp16(uint32_t dst, const void* src) {
    asm volatile("cp.async.cg.shared.global [%0], [%1], 16;"
                 :: "r"(dst), "l"(__cvta_generic_to_global(src)));
}
__device__ __forceinline__ void cp_commit() {
    asm volatile("cp.async.commit_group;");
}
template <int N>
__device__ __forceinline__ void cp_wait() {
    asm volatile("cp.async.wait_group %0;" :: "n"(N));
}
__device__ __forceinline__ void ldsm_x4(unsigned& r0, unsigned& r1, unsigned& r2,
                                        unsigned& r3, uint32_t addr) {
    asm volatile("ldmatrix.sync.aligned.m8n8.x4.shared.b16 {%0,%1,%2,%3}, [%4];"
                 : "=r"(r0), "=r"(r1), "=r"(r2), "=r"(r3) : "r"(addr));
}
__device__ __forceinline__ void mma16816(float* c, const unsigned* a, const unsigned* b) {
    asm volatile(
        "mma.sync.aligned.m16n8k16.row.col.f32.f16.f16.f32 "
        "{%0,%1,%2,%3}, {%4,%5,%6,%7}, {%8,%9}, {%0,%1,%2,%3};"
        : "+f"(c[0]), "+f"(c[1]), "+f"(c[2]), "+f"(c[3])
        : "r"(a[0]), "r"(a[1]), "r"(a[2]), "r"(a[3]), "r"(b[0]), "r"(b[1]));
}

// ---------------------------------------------------------------------------
// MMA compute over one k32 stage.
// NPASS==1: ah*bh only.        A at abase,       B at bbase.
// NPASS==3: + al*bh + ah*bl.   Al at abase+MATB, Bl at bbase+MATB.
// ---------------------------------------------------------------------------
template <int NPASS>
__device__ __forceinline__ void mma_stage(uint32_t abase, uint32_t bbase,
                                          float acc[2][8][4]) {
    const int lane = threadIdx.x & 31, wid = threadIdx.x >> 5;
    const int mw = (wid >> 1) * 32, nw = (wid & 1) * 64;
    const int lr = lane & 7, q = lane >> 3;
    const int a_ro = (q & 1) * 8 + lr, a_co = (q >> 1);
    const int b_ro = (q >> 1) * 8 + lr, b_co = (q & 1);
    #pragma unroll
    for (int ks = 0; ks < 2; ++ks) {
        unsigned ah[2][4], al[2][4];
        #pragma unroll
        for (int mt = 0; mt < 2; ++mt) {
            uint32_t ad = abase + (uint32_t)((mw + mt * 16 + a_ro) * 80 + (2 * ks + a_co) * 16);
            ldsm_x4(ah[mt][0], ah[mt][1], ah[mt][2], ah[mt][3], ad);
            if (NPASS == 3)
                ldsm_x4(al[mt][0], al[mt][1], al[mt][2], al[mt][3], ad + MATB);
        }
        unsigned bh[8][2], bl[8][2];
        #pragma unroll
        for (int np = 0; np < 4; ++np) {
            uint32_t bd = bbase + (uint32_t)((nw + np * 16 + b_ro) * 80 + (2 * ks + b_co) * 16);
            ldsm_x4(bh[2*np][0], bh[2*np][1], bh[2*np+1][0], bh[2*np+1][1], bd);
            if (NPASS == 3)
                ldsm_x4(bl[2*np][0], bl[2*np][1], bl[2*np+1][0], bl[2*np+1][1], bd + MATB);
        }
        #pragma unroll
        for (int nt = 0; nt < 8; ++nt)
            #pragma unroll
            for (int mt = 0; mt < 2; ++mt) {
                mma16816(acc[mt][nt], ah[mt], bh[nt]);
                if (NPASS == 3) {
                    mma16816(acc[mt][nt], al[mt], bh[nt]);
                    mma16816(acc[mt][nt], ah[mt], bl[nt]);
                }
            }
    }
}

// ---------------------------------------------------------------------------
// Pre-split fp16 planes in gmem, all via cp.async.
// NPASS==1: stage = {Ah, Bh};  NPASS==3: stage = {Ah, Al, Bh, Bl}.
// ---------------------------------------------------------------------------
template <int NPASS>
__device__ __forceinline__ void mma_loop(
    const __half* __restrict__ Agh, const __half* __restrict__ Agl, int lda, int m0,
    const __half* __restrict__ Bgh, const __half* __restrict__ Bgl, int ldb, int n0,
    int kIters, char* smb, float acc[2][8][4])
{
    const int BOFF = (NPASS == 3 ? 2 : 1) * MATB;
    const int STAGE = (NPASS == 3 ? 4 : 2) * MATB;
    const int t = threadIdx.x;
    const int r = t >> 1, cb = (t & 1) * 2;
    const __half* pa_h = Agh + (size_t)(m0 + r) * lda + cb * 8;
    const __half* pa_l = (NPASS == 3) ? Agl + (size_t)(m0 + r) * lda + cb * 8 : pa_h;
    const __half* pb_h = Bgh + (size_t)(n0 + r) * ldb + cb * 8;
    const __half* pb_l = (NPASS == 3) ? Bgl + (size_t)(n0 + r) * ldb + cb * 8 : pb_h;
    const uint32_t sbase = smem_u32(smb);
    const uint32_t rowoff = (uint32_t)r * 80u + (uint32_t)cb * 16u;

    auto issue = [&](int it) {
        uint32_t sb = sbase + (uint32_t)((it % NSTAGE) * STAGE) + rowoff;
        int k0 = it * 32;
        #pragma unroll
        for (int j = 0; j < 2; ++j) {
            cp16(sb + j * 16,        pa_h + k0 + j * 8);
            cp16(sb + BOFF + j * 16, pb_h + k0 + j * 8);
            if (NPASS == 3) {
                cp16(sb + MATB + j * 16,     pa_l + k0 + j * 8);
                cp16(sb + 3 * MATB + j * 16, pb_l + k0 + j * 8);
            }
        }
    };
    issue(0); cp_commit();
    issue(1); cp_commit();

    for (int it = 0; it < kIters; ++it) {
        cp_wait<1>();
        __syncthreads();
        if (it + 2 < kIters) issue(it + 2);
        cp_commit();
        uint32_t sb = sbase + (uint32_t)((it % NSTAGE) * STAGE);
        mma_stage<NPASS>(sb, sb + BOFF, acc);
    }
}

// ---------------------------------------------------------------------------
// Kernel 0a: X -> Xh, Xl (B,T,E) and Xth (B,E,T)
// ---------------------------------------------------------------------------
__global__ void prep_x_kernel(const float* __restrict__ X) {
    __shared__ float tile[32][33];
    int b = blockIdx.z;
    int e0 = blockIdx.x * 32, t0 = blockIdx.y * 32;
    const float* Xb = X + (size_t)b * Tq * Eq;
    int tx = threadIdx.x, ty = threadIdx.y;  // 32x8
    #pragma unroll
    for (int i = 0; i < 32; i += 8) {
        float v = Xb[(size_t)(t0 + ty + i) * Eq + e0 + tx];
        tile[ty + i][tx] = v;
        __half h = __float2half_rn(v);
        __half l = __float2half_rn(v - __half2float(h));
        size_t idx = ((size_t)b * Tq + t0 + ty + i) * Eq + e0 + tx;
        g_xh[idx] = h;
        g_xl[idx] = l;
    }
    __syncthreads();
    #pragma unroll
    for (int i = 0; i < 32; i += 8) {
        float v = tile[tx][ty + i];
        g_xth[((size_t)b * Eq + e0 + ty + i) * Tq + t0 + tx] = __float2half_rn(v);
    }
}

// Kernel 0b: W -> Wh
__global__ void prep_w_kernel(const float* __restrict__ W) {
    int idx = blockIdx.x * 256 + threadIdx.x;
    g_wh[idx] = __float2half_rn(W[idx]);
}

// ---------------------------------------------------------------------------
// Kernel 1: G_b = mask-outer ? (X_b X_b^T)/sqrt(E) : 0   (3-pass fp16, K=256)
// ---------------------------------------------------------------------------
__global__ __launch_bounds__(256, 1)
void gram_kernel(const int* __restrict__ mask) {
    extern __shared__ char smb[];
    int b = blockIdx.z;
    int m0 = blockIdx.y * 128, n0 = blockIdx.x * 128;
    const __half* Xh = g_xh + (size_t)b * Tq * Eq;
    const __half* Xl = g_xl + (size_t)b * Tq * Eq;
    float acc[2][8][4] = {};
    mma_loop<3>(Xh, Xl, Eq, m0, Xh, Xl, Eq, n0, Eq / 32, smb, acc);

    const int lane = threadIdx.x & 31, wid = threadIdx.x >> 5;
    const int gid = lane >> 2, tig = lane & 3;
    const int mw = (wid >> 1) * 32, nw = (wid & 1) * 64;
    const int* mb = mask + b * Tq;
    float* G = g_gram + (size_t)b * Tq * Tq;
    #pragma unroll
    for (int mt = 0; mt < 2; ++mt) {
        int mr0 = m0 + mw + mt * 16 + gid;
        int mr1 = mr0 + 8;
        float s0 = (mb[mr0] != 0) ? 0.0625f : 0.0f;   // 1/sqrt(256), fold row mask
        float s1 = (mb[mr1] != 0) ? 0.0625f : 0.0f;
        #pragma unroll
        for (int nt = 0; nt < 8; ++nt) {
            int col = n0 + nw + nt * 8 + 2 * tig;
            float c0 = (mb[col] != 0) ? 1.0f : 0.0f;
            float c1 = (mb[col + 1] != 0) ? 1.0f : 0.0f;
            *(float2*)&G[(size_t)mr0 * Tq + col] =
                make_float2(acc[mt][nt][0] * s0 * c0, acc[mt][nt][1] * s0 * c1);
            *(float2*)&G[(size_t)mr1 * Tq + col] =
                make_float2(acc[mt][nt][2] * s1 * c0, acc[mt][nt][3] * s1 * c1);
        }
    }
}

// ---------------------------------------------------------------------------
// Kernel 2: softmax, warp-per-attribute. 8 warps = 8 attributes; each warp
// holds the whole 512-row in registers, warp-only reductions, zero barriers.
// Writes fp32 attn (output) + fp16 hi plane (av's A operand).
// ---------------------------------------------------------------------------
__global__ __launch_bounds__(256, 8)
void softmax_kernel(const float* __restrict__ atr, float* __restrict__ attn) {
    int t = blockIdx.x, b = blockIdx.y;
    int wid = threadIdx.x >> 5, lane = threadIdx.x & 31;
    const float4* g4 = (const float4*)(g_gram + ((size_t)b * Tq + t) * Tq);
    float4 v[4];
    #pragma unroll
    for (int j = 0; j < 4; ++j) v[j] = g4[lane + 32 * j];

    float m = v[0].x;
    #pragma unroll
    for (int j = 0; j < 4; ++j) {
        m = fmaxf(m, fmaxf(fmaxf(v[j].x, v[j].y), fmaxf(v[j].z, v[j].w)));
    }
    #pragma unroll
    for (int off = 16; off; off >>= 1) m = fmaxf(m, __shfl_xor_sync(0xffffffffu, m, off));

    float s = atr[b * Aq + wid];
    float s2 = s * s;
    float4 e[4];
    float sum = 0.0f;
    #pragma unroll
    for (int j = 0; j < 4; ++j) {
        e[j].x = __expf(s2 * (v[j].x - m));
        e[j].y = __expf(s2 * (v[j].y - m));
        e[j].z = __expf(s2 * (v[j].z - m));
        e[j].w = __expf(s2 * (v[j].w - m));
        sum += e[j].x + e[j].y + e[j].z + e[j].w;
    }
    #pragma unroll
    for (int off = 16; off; off >>= 1) sum += __shfl_xor_sync(0xffffffffu, sum, off);
    float inv = 1.0f / sum;

    size_t rowbase = (((size_t)(b * Aq + wid) * Tq) + t) * Tq;
    float4* o4 = (float4*)(attn + rowbase);
    uint2*  h2 = (uint2*)(g_attn_h + rowbase);
    #pragma unroll
    for (int j = 0; j < 4; ++j) {
        float4 o = make_float4(e[j].x * inv, e[j].y * inv, e[j].z * inv, e[j].w * inv);
        o4[lane + 32 * j] = o;
        __half2 ha = __float22half2_rn(make_float2(o.x, o.y));
        __half2 hb = __float22half2_rn(make_float2(o.z, o.w));
        h2[lane + 32 * j] = make_uint2(*(unsigned*)&ha, *(unsigned*)&hb);
    }
}

// ---------------------------------------------------------------------------
// Kernel 3: attn_out[ba] = s_ba * (attn_ba @ X_b); 1-pass, all-cp.async
// ---------------------------------------------------------------------------
__global__ __launch_bounds__(256, 2)
void av_kernel(const float* __restrict__ atr) {
    extern __shared__ char smb[];
    int ba = blockIdx.z, b = ba >> 3;
    int m0 = blockIdx.y * 128, n0 = blockIdx.x * 128;
    const __half* Ah = g_attn_h + (size_t)ba * Tq * Tq;
    const __half* Bh = g_xth + (size_t)b * Eq * Tq;
    float acc[2][8][4] = {};
    mma_loop<1>(Ah, nullptr, Tq, m0, Bh, nullptr, Tq, n0, Tq / 32, smb, acc);

    const int lane = threadIdx.x & 31, wid = threadIdx.x >> 5;
    const int gid = lane >> 2, tig = lane & 3;
    const int mw = (wid >> 1) * 32, nw = (wid & 1) * 64;
    float sc = atr[ba];
    #pragma unroll
    for (int mt = 0; mt < 2; ++mt) {
        int mr0 = m0 + mw + mt * 16 + gid;
        int mr1 = mr0 + 8;
        #pragma unroll
        for (int nt = 0; nt < 8; ++nt) {
            int col = n0 + nw + nt * 8 + 2 * tig;
            size_t i0 = ((size_t)ba * Tq + mr0) * Eq + col;
            size_t i1 = ((size_t)ba * Tq + mr1) * Eq + col;
            *(__half2*)&g_aoh[i0] = __float22half2_rn(
                make_float2(sc * acc[mt][nt][0], sc * acc[mt][nt][1]));
            *(__half2*)&g_aoh[i1] = __float22half2_rn(
                make_float2(sc * acc[mt][nt][2], sc * acc[mt][nt][3]));
        }
    }
}

// ---------------------------------------------------------------------------
// Kernel 4: out = aoh(8192x2048) @ Wh^T(2048x256) + bias (full K, 1-pass)
// ---------------------------------------------------------------------------
__global__ __launch_bounds__(256, 2)
void proj_kernel(const float* __restrict__ bias, float* __restrict__ out) {
    extern __shared__ char smb[];
    const int Kd = Aq * Eq;  // 2048
    int m0 = blockIdx.y * 128, n0 = blockIdx.x * 128;
    float acc[2][8][4] = {};
    mma_loop<1>(g_aoh, nullptr, Kd, m0, g_wh, nullptr, Kd, n0, Kd / 32, smb, acc);

    const int lane = threadIdx.x & 31, wid = threadIdx.x >> 5;
    const int gid = lane >> 2, tig = lane & 3;
    const int mw = (wid >> 1) * 32, nw = (wid & 1) * 64;
    #pragma unroll
    for (int mt = 0; mt < 2; ++mt) {
        int mr0 = m0 + mw + mt * 16 + gid;
        int mr1 = mr0 + 8;
        #pragma unroll
        for (int nt = 0; nt < 8; ++nt) {
            int col = n0 + nw + nt * 8 + 2 * tig;
            float b0 = bias[col], b1 = bias[col + 1];
            *(float2*)&out[(size_t)mr0 * Eq + col] =
                make_float2(acc[mt][nt][0] + b0, acc[mt][nt][1] + b1);
            *(float2*)&out[(size_t)mr1 * Eq + col] =
                make_float2(acc[mt][nt][2] + b0, acc[mt][nt][3] + b1);
        }
    }
}

// ---------------------------------------------------------------------------
extern "C" void kernel_launch(void* const* d_in, const int* in_sizes, int n_in,
                              void* d_out, int out_size) {
    const float* sent = (const float*)d_in[0];
    const int*   mask = (const int*)d_in[1];
    const float* atr  = (const float*)d_in[2];
    const float* W    = (const float*)d_in[3];
    const float* bias = (const float*)d_in[4];
    float* out = (float*)d_out;

    const long long OUT_E  = (long long)Bq * Tq * Eq;        // 2,097,152
    const long long ATTN_E = (long long)Bq * Aq * Tq * Tq;   // 33,554,432

    float* attn_ptr;
    if ((long long)out_size >= OUT_E + ATTN_E) {
        attn_ptr = out + OUT_E;                  // tuple (output, attn) flattened
    } else {
        void* p = nullptr;
        cudaGetSymbolAddress(&p, g_attn_fb);     // query only, capture-safe
        attn_ptr = (float*)p;
    }

    const int SM3 = 3 * 4 * MATB;   // 122880 (gram 3-pass: 3 stages x 4 mats)
    const int SM1 = 3 * 2 * MATB;   // 61440  (1-pass: 3 stages x 2 mats)
    cudaFuncSetAttribute(gram_kernel, cudaFuncAttributeMaxDynamicSharedMemorySize, SM3);
    cudaFuncSetAttribute(av_kernel,   cudaFuncAttributeMaxDynamicSharedMemorySize, SM1);
    cudaFuncSetAttribute(proj_kernel, cudaFuncAttributeMaxDynamicSharedMemorySize, SM1);

    prep_x_kernel<<<dim3(Eq / 32, Tq / 32, Bq), dim3(32, 8)>>>(sent);
    prep_w_kernel<<<(Eq * Aq * Eq) / 256, 256>>>(W);
    gram_kernel<<<dim3(Tq / 128, Tq / 128, Bq), 256, SM3>>>(mask);
    softmax_kernel<<<dim3(Tq, Bq), 256>>>(atr, attn_ptr);
    av_kernel<<<dim3(Eq / 128, Tq / 128, Bq * Aq), 256, SM1>>>(atr);
    proj_kernel<<<dim3(Eq / 128, (Bq * Tq) / 128, 1), 256, SM1>>>(bias, out);
}